// round 12
// baseline (speedup 1.0000x reference)
#include <cuda_runtime.h>
#include <cuda_bf16.h>
#include <math.h>

// ---------------------------------------------------------------------------
// SimplifiedSSMLayer: B=8, S=4096, D_MODEL=1024, D_STATE=16
// Round 12:
//   K1 = self-contained scan blocks (0..511: inline Bx from x/B_w into smem,
//        then 64-warm chunked recurrence) + GEMM 2048 tiles (round-5 body).
//        No bx kernel, no standalone scan kernel, no cross-block ordering.
//   K3 = combine+LN (round-11 cp.async staged version).
// ---------------------------------------------------------------------------

#define BATCH   8
#define SEQ     4096
#define DM      1024
#define NS      16
#define T_TOK   (BATCH*SEQ)          // 32768

__device__ float g_states[T_TOK * NS];           // 2 MB
__device__ float g_gate[(size_t)T_TOK * DM];     // 128 MB

#define SCANB 512                          // one chunk per block

#define GTM 128
#define GTN 128
#define GBK 32
#define GSTAGES (DM / GBK)                // 32
#define GEMM_BLOCKS 2048

#define ROWSTRIDE 36                      // floats; ldsm conflict-free
#define A_FLOATS (GTM * ROWSTRIDE)        // 4608
#define STAGE_FLOATS (2 * A_FLOATS)       // 9216
#define STAGE_BYTES (STAGE_FLOATS * 4)    // 36864
#define NPIPE 3
#define GEMM_SMEM (NPIPE * STAGE_BYTES)   // 110592 -> 2 CTAs/SM

#define SCAN_CHUNK 64
#define SCAN_WARM  64

#define K3_SMEM (2 * 8 * DM * 4)          // 65536: x_s + g_s

__device__ __forceinline__ unsigned smem_u32(const void* p) {
    unsigned a;
    asm("{ .reg .u64 t; cvta.to.shared.u64 t, %1; cvt.u32.u64 %0, t; }"
        : "=r"(a) : "l"(p));
    return a;
}
__device__ __forceinline__ void cp16(unsigned dst, const void* src) {
    asm volatile("cp.async.cg.shared.global [%0], [%1], 16;"
                 :: "r"(dst), "l"(src) : "memory");
}
__device__ __forceinline__ void ldsm4(unsigned& r0, unsigned& r1,
                                      unsigned& r2, unsigned& r3, unsigned a) {
    asm volatile("ldmatrix.sync.aligned.m8n8.x4.shared.b16 {%0,%1,%2,%3}, [%4];"
                 : "=r"(r0), "=r"(r1), "=r"(r2), "=r"(r3) : "r"(a));
}

// ---------------------------------------------------------------------------
// GEMM tile body — round-5 configuration, verbatim inner loop
// ---------------------------------------------------------------------------
__device__ __forceinline__ void gemm_tile_body(
    int tile, const float* __restrict__ x,
    const float* __restrict__ gate_w, const float* __restrict__ gate_b,
    float* smemf)
{
    const int m0 = (tile >> 3) * GTM;
    const int n0 = (tile & 7) * GTN;

    const int tid = threadIdx.x;
    const int wid = tid >> 5;
    const int lane = tid & 31;
    const int wm = (wid & 3) * 32;
    const int wn = (wid >> 2) * 64;
    const int lq = lane >> 2;
    const int lr = lane & 3;

    const unsigned sbase = smem_u32(smemf);

    const int a_row = wm + (lane & 7) + ((lane >> 3) & 1) * 8;   // + mi*16
    const int a_kx  = (lane >> 4) * 4;
    const int b_row = wn + (lane & 7) + ((lane >> 4) & 1) * 8;   // + nip*16
    const int b_kx  = ((lane >> 3) & 1) * 4;

    auto cp_stage = [&](int s) {
        const int kc = s * GBK;
        const unsigned sA = sbase + (unsigned)(s % NPIPE) * STAGE_BYTES;
        const unsigned sB = sA + A_FLOATS * 4;
#pragma unroll
        for (int q = 0; q < 4; ++q) {
            const int j = tid + 256 * q;
            const int row = j >> 3;
            const int kg = j & 7;
            cp16(sA + row * (ROWSTRIDE * 4) + kg * 16,
                 &x[(size_t)(m0 + row) * DM + kc + kg * 4]);
            cp16(sB + row * (ROWSTRIDE * 4) + kg * 16,
                 &gate_w[(size_t)(n0 + row) * DM + kc + kg * 4]);
        }
        asm volatile("cp.async.commit_group;" ::: "memory");
    };

    float c[2][8][4];
#pragma unroll
    for (int mi = 0; mi < 2; ++mi)
#pragma unroll
        for (int ni = 0; ni < 8; ++ni)
#pragma unroll
            for (int r = 0; r < 4; ++r) c[mi][ni][r] = 0.f;

    cp_stage(0);
    cp_stage(1);

    for (int s = 0; s < GSTAGES; ++s) {
        asm volatile("cp.async.wait_group 1;" ::: "memory");
        __syncthreads();

        const unsigned stg = sbase + (unsigned)(s % NPIPE) * STAGE_BYTES;
        const unsigned aAddr0 = stg + (unsigned)((a_row)*ROWSTRIDE + a_kx) * 4u;
        const unsigned bAddr0 = stg + (unsigned)(A_FLOATS + (b_row)*ROWSTRIDE + b_kx) * 4u;

#pragma unroll
        for (int ks = 0; ks < 4; ++ks) {
            const int k0 = ks * 8;
            unsigned af[2][4];
#pragma unroll
            for (int mi = 0; mi < 2; ++mi)
                ldsm4(af[mi][0], af[mi][1], af[mi][2], af[mi][3],
                      aAddr0 + (unsigned)(mi * 16 * ROWSTRIDE + k0) * 4u);
            unsigned bf[8][2];
#pragma unroll
            for (int nip = 0; nip < 4; ++nip)
                ldsm4(bf[nip * 2][0], bf[nip * 2][1],
                      bf[nip * 2 + 1][0], bf[nip * 2 + 1][1],
                      bAddr0 + (unsigned)(nip * 16 * ROWSTRIDE + k0) * 4u);
#pragma unroll
            for (int mi = 0; mi < 2; ++mi)
#pragma unroll
                for (int ni = 0; ni < 8; ++ni) {
                    asm volatile(
                        "mma.sync.aligned.m16n8k8.row.col.f32.tf32.tf32.f32 "
                        "{%0,%1,%2,%3}, {%4,%5,%6,%7}, {%8,%9}, {%0,%1,%2,%3};"
                        : "+f"(c[mi][ni][0]), "+f"(c[mi][ni][1]),
                          "+f"(c[mi][ni][2]), "+f"(c[mi][ni][3])
                        : "r"(af[mi][0]), "r"(af[mi][1]),
                          "r"(af[mi][2]), "r"(af[mi][3]),
                          "r"(bf[ni][0]), "r"(bf[ni][1]));
                }
        }
        if (s + 2 < GSTAGES) cp_stage(s + 2);
    }

#pragma unroll
    for (int ni = 0; ni < 8; ++ni) {
        const int col = n0 + wn + ni * 8 + lr * 2;
        const float2 gb = *reinterpret_cast<const float2*>(&gate_b[col]);
#pragma unroll
        for (int mi = 0; mi < 2; ++mi) {
            const int row0 = m0 + wm + mi * 16 + lq;
#pragma unroll
            for (int h = 0; h < 2; ++h) {
                const int row = row0 + h * 8;
                float z0 = c[mi][ni][h * 2 + 0] + gb.x;
                float z1 = c[mi][ni][h * 2 + 1] + gb.y;
                float2 o;
                o.x = z0 / (1.0f + __expf(-z0));
                o.y = z1 / (1.0f + __expf(-z1));
                *reinterpret_cast<float2*>(&g_gate[(size_t)row * DM + col]) = o;
            }
        }
    }
}

// ---------------------------------------------------------------------------
// K1: self-contained scan blocks (0..511) + GEMM tiles (512..2559)
// ---------------------------------------------------------------------------
__global__ void __launch_bounds__(256, 2) k1_kernel(
    const float* __restrict__ x, const float* __restrict__ A,
    const float* __restrict__ B_w, const float* __restrict__ B_b,
    const float* __restrict__ gate_w, const float* __restrict__ gate_b)
{
    extern __shared__ float smemf[];
    const int tid = threadIdx.x;

    if (blockIdx.x < SCANB) {
        // ============ scan block: inline Bx (phase 1) + recurrence ==========
        const int chunk = blockIdx.x;          // 0..511
        const int batch = chunk >> 6;
        const int cib = chunk & 63;
        const int t0 = cib * SCAN_CHUNK;
        const int ts = (cib == 0) ? 0 : (t0 - SCAN_WARM);
        const size_t tokbase = (size_t)batch * SEQ;

        float* Bw_s = smemf;                   // [16][1024] = 64KB
        float* bx_s = smemf + NS * DM;         // [128][16]  = 8KB

        for (int i = tid; i < (NS * DM) / 4; i += 256)
            reinterpret_cast<float4*>(Bw_s)[i] = reinterpret_cast<const float4*>(B_w)[i];
        __syncthreads();

        // phase 1: Bx for 128 tokens [ts, ts+128), 8 warps x 16 tokens
        const int w = tid >> 5, lane = tid & 31;
        for (int g = 0; g < 4; ++g) {
            const int lt0 = w * 16 + g * 4;    // local token base (0..124)
            float acc[4][NS];
#pragma unroll
            for (int tt = 0; tt < 4; ++tt)
#pragma unroll
                for (int n = 0; n < NS; ++n) acc[tt][n] = 0.f;

#pragma unroll 2
            for (int c = 0; c < 8; ++c) {
                const int k0 = c * 128 + lane * 4;
                float4 xv[4];
#pragma unroll
                for (int tt = 0; tt < 4; ++tt)
                    xv[tt] = *reinterpret_cast<const float4*>(
                        &x[(tokbase + ts + lt0 + tt) * DM + k0]);
#pragma unroll
                for (int n = 0; n < NS; ++n) {
                    const float4 bw = *reinterpret_cast<const float4*>(&Bw_s[n * DM + k0]);
#pragma unroll
                    for (int tt = 0; tt < 4; ++tt) {
                        acc[tt][n] = fmaf(xv[tt].x, bw.x, acc[tt][n]);
                        acc[tt][n] = fmaf(xv[tt].y, bw.y, acc[tt][n]);
                        acc[tt][n] = fmaf(xv[tt].z, bw.z, acc[tt][n]);
                        acc[tt][n] = fmaf(xv[tt].w, bw.w, acc[tt][n]);
                    }
                }
            }
#pragma unroll
            for (int tt = 0; tt < 4; ++tt) {
                float outv = 0.f;
#pragma unroll
                for (int n = 0; n < NS; ++n) {
                    float v = acc[tt][n];
                    v += __shfl_xor_sync(0xffffffffu, v, 16);
                    v += __shfl_xor_sync(0xffffffffu, v, 8);
                    v += __shfl_xor_sync(0xffffffffu, v, 4);
                    v += __shfl_xor_sync(0xffffffffu, v, 2);
                    v += __shfl_xor_sync(0xffffffffu, v, 1);
                    if (lane == n) outv = v;
                }
                if (lane < NS)
                    bx_s[(lt0 + tt) * NS + lane] = outv + B_b[lane];
            }
        }
        __syncthreads();

        // phase 2: warp 0 runs the recurrence (both 16-lane halves duplicate)
        if (w == 0) {
            const int i = lane & 15;
            float a[NS];
#pragma unroll
            for (int j = 0; j < NS; ++j) a[j] = __ldg(&A[i * NS + j]);

            float s = 0.f;
            for (int t = ts; t < t0 + SCAN_CHUNK; ++t) {
                const float bx = bx_s[(t - ts) * NS + i];
                float sv[NS];
#pragma unroll
                for (int j = 0; j < NS; ++j) sv[j] = __shfl_sync(0xffffffffu, s, j, 16);
                float p0 = fmaf(a[0], sv[0], fmaf(a[1], sv[1], fmaf(a[2], sv[2], a[3] * sv[3])));
                float p1 = fmaf(a[4], sv[4], fmaf(a[5], sv[5], fmaf(a[6], sv[6], a[7] * sv[7])));
                float p2 = fmaf(a[8], sv[8], fmaf(a[9], sv[9], fmaf(a[10], sv[10], a[11] * sv[11])));
                float p3 = fmaf(a[12], sv[12], fmaf(a[13], sv[13], fmaf(a[14], sv[14], a[15] * sv[15])));
                s = tanhf(bx + ((p0 + p1) + (p2 + p3)));
                if (t >= t0) g_states[(tokbase + t) * NS + i] = s;
            }
        }
        return;
    }

    gemm_tile_body(blockIdx.x - SCANB, x, gate_w, gate_b, smemf);
}

// ---------------------------------------------------------------------------
// K3: combine + LayerNorm, cp.async bulk-staged (round-11 version).
// ---------------------------------------------------------------------------
__global__ void __launch_bounds__(256) combine_ln_kernel(
    const float* __restrict__ x, const float* __restrict__ C_w,
    const float* __restrict__ C_b, const float* __restrict__ Dv,
    const float* __restrict__ ln_g, const float* __restrict__ ln_b,
    float* __restrict__ out)
{
    extern __shared__ float k3s[];
    float* x_s = k3s;             // 8*1024
    float* g_s = k3s + 8 * DM;    // 8*1024

    __shared__ float st_s[8][NS];
    __shared__ float wsum[8][8], wsq[8][8];
    __shared__ float mu_s[8], rs_s[8];

    const int tid = threadIdx.x;
    const int tok0 = blockIdx.x * 8;
    const int e0 = tid * 4;
    const unsigned sb = smem_u32(k3s);

#pragma unroll
    for (int q = 0; q < 8; ++q) {
        const int idx = tid + 256 * q;          // 0..2047 chunks of 16B
        const int row = idx >> 8;
        const int c16 = idx & 255;
        cp16(sb + (unsigned)idx * 16u,
             &x[(size_t)(tok0 + row) * DM + c16 * 4]);
        cp16(sb + 32768u + (unsigned)idx * 16u,
             &g_gate[(size_t)(tok0 + row) * DM + c16 * 4]);
    }
    asm volatile("cp.async.commit_group;" ::: "memory");

    if (tid < 128)
        st_s[tid >> 4][tid & 15] =
            g_states[(size_t)(tok0 + (tid >> 4)) * NS + (tid & 15)];

    float cw[4][NS];
#pragma unroll
    for (int j = 0; j < 4; ++j)
#pragma unroll
        for (int n4 = 0; n4 < 4; ++n4) {
            const float4 v = *reinterpret_cast<const float4*>(&C_w[(e0 + j) * NS + n4 * 4]);
            cw[j][n4 * 4 + 0] = v.x;
            cw[j][n4 * 4 + 1] = v.y;
            cw[j][n4 * 4 + 2] = v.z;
            cw[j][n4 * 4 + 3] = v.w;
        }
    const float4 cb4 = *reinterpret_cast<const float4*>(&C_b[e0]);
    const float4 dv4 = *reinterpret_cast<const float4*>(&Dv[e0]);
    const float4 lg4 = *reinterpret_cast<const float4*>(&ln_g[e0]);
    const float4 lb4 = *reinterpret_cast<const float4*>(&ln_b[e0]);

    asm volatile("cp.async.wait_group 0;" ::: "memory");
    __syncthreads();

    const int warp = tid >> 5, lane = tid & 31;
#pragma unroll 2
    for (int r = 0; r < 8; ++r) {
        const float4 xv = *reinterpret_cast<const float4*>(&x_s[r * DM + e0]);
        const float4 gv = *reinterpret_cast<const float4*>(&g_s[r * DM + e0]);

        float so[4] = {cb4.x, cb4.y, cb4.z, cb4.w};
#pragma unroll
        for (int n = 0; n < NS; ++n) {
            const float st = st_s[r][n];
            so[0] = fmaf(st, cw[0][n], so[0]);
            so[1] = fmaf(st, cw[1][n], so[1]);
            so[2] = fmaf(st, cw[2][n], so[2]);
            so[3] = fmaf(st, cw[3][n], so[3]);
        }
        so[0] = fmaf(dv4.x, xv.x, so[0]);
        so[1] = fmaf(dv4.y, xv.y, so[1]);
        so[2] = fmaf(dv4.z, xv.z, so[2]);
        so[3] = fmaf(dv4.w, xv.w, so[3]);

        float4 rr;
        rr.x = fmaf(gv.x, so[0] - xv.x, xv.x) + xv.x;
        rr.y = fmaf(gv.y, so[1] - xv.y, xv.y) + xv.y;
        rr.z = fmaf(gv.z, so[2] - xv.z, xv.z) + xv.z;
        rr.w = fmaf(gv.w, so[3] - xv.w, xv.w) + xv.w;
        *reinterpret_cast<float4*>(&g_s[r * DM + e0]) = rr;  // overwrite gate

        float ps = (rr.x + rr.y) + (rr.z + rr.w);
        float pq = fmaf(rr.x, rr.x, rr.y * rr.y) + fmaf(rr.z, rr.z, rr.w * rr.w);
#pragma unroll
        for (int off = 16; off; off >>= 1) {
            ps += __shfl_xor_sync(0xffffffffu, ps, off);
            pq += __shfl_xor_sync(0xffffffffu, pq, off);
        }
        if (lane == 0) { wsum[r][warp] = ps; wsq[r][warp] = pq; }
    }
    __syncthreads();

    if (tid < 8) {
        float s = 0.f, s2 = 0.f;
#pragma unroll
        for (int w = 0; w < 8; ++w) { s += wsum[tid][w]; s2 += wsq[tid][w]; }
        const float mu = s * (1.0f / DM);
        float var = s2 * (1.0f / DM) - mu * mu;
        var = fmaxf(var, 0.f);
        mu_s[tid] = mu;
        rs_s[tid] = rsqrtf(var + 1e-5f);
    }
    __syncthreads();

#pragma unroll 2
    for (int r = 0; r < 8; ++r) {
        const size_t t = (size_t)(tok0 + r);
        const float mu = mu_s[r], rs = rs_s[r];
        const float4 rr = *reinterpret_cast<const float4*>(&g_s[r * DM + e0]);
        float4 o;
        o.x = (rr.x - mu) * rs * lg4.x + lb4.x;
        o.y = (rr.y - mu) * rs * lg4.y + lb4.y;
        o.z = (rr.z - mu) * rs * lg4.z + lb4.z;
        o.w = (rr.w - mu) * rs * lg4.w + lb4.w;
        *reinterpret_cast<float4*>(&out[t * DM + e0]) = o;
    }
}

// ---------------------------------------------------------------------------
extern "C" void kernel_launch(void* const* d_in, const int* in_sizes, int n_in,
                              void* d_out, int out_size)
{
    const float* x      = (const float*)d_in[0];
    const float* A      = (const float*)d_in[1];
    const float* B_w    = (const float*)d_in[2];
    const float* B_b    = (const float*)d_in[3];
    const float* C_w    = (const float*)d_in[4];
    const float* C_b    = (const float*)d_in[5];
    const float* Dv     = (const float*)d_in[6];
    const float* gate_w = (const float*)d_in[7];
    const float* gate_b = (const float*)d_in[8];
    const float* ln_g   = (const float*)d_in[9];
    const float* ln_b   = (const float*)d_in[10];
    float* out = (float*)d_out;

    cudaFuncSetAttribute(k1_kernel, cudaFuncAttributeMaxDynamicSharedMemorySize,
                         GEMM_SMEM);
    cudaFuncSetAttribute(combine_ln_kernel, cudaFuncAttributeMaxDynamicSharedMemorySize,
                         K3_SMEM);

    k1_kernel<<<SCANB + GEMM_BLOCKS, 256, GEMM_SMEM>>>(x, A, B_w, B_b, gate_w, gate_b);
    combine_ln_kernel<<<T_TOK / 8, 256, K3_SMEM>>>(x, C_w, C_b, Dv, ln_g, ln_b, out);
}

// round 13
// speedup vs baseline: 1.0643x; 1.0643x over previous
#include <cuda_runtime.h>
#include <cuda_fp16.h>
#include <math.h>

// ---------------------------------------------------------------------------
// SimplifiedSSMLayer: B=8, S=4096, D_MODEL=1024, D_STATE=16
// Round 13:
//   K1 = bx (blocks 0..255) + GEMM 2048 tiles (round-5 body), gate -> fp16
//   K2 = standalone scan, warm=16/chunk=32, group-of-4 Bx prefetch
//   K3 = combine+LN, direct LDG (round-8 style), fp16 gate reads
// ---------------------------------------------------------------------------

#define BATCH   8
#define SEQ     4096
#define DM      1024
#define NS      16
#define T_TOK   (BATCH*SEQ)          // 32768

__device__ float  g_Bx[T_TOK * NS];              // 2 MB
__device__ float  g_states[T_TOK * NS];          // 2 MB
__device__ __half g_gate_h[(size_t)T_TOK * DM];  // 64 MB

#define BX_GRID 256

#define GTM 128
#define GTN 128
#define GBK 32
#define GSTAGES (DM / GBK)                // 32
#define GEMM_BLOCKS 2048

#define ROWSTRIDE 36                      // floats; ldsm conflict-free
#define A_FLOATS (GTM * ROWSTRIDE)        // 4608
#define STAGE_FLOATS (2 * A_FLOATS)       // 9216
#define STAGE_BYTES (STAGE_FLOATS * 4)    // 36864
#define NPIPE 3
#define GEMM_SMEM (NPIPE * STAGE_BYTES)   // 110592 -> 2 CTAs/SM

#define SCAN_CHUNK 32
#define SCAN_WARM  16
#define SCAN_CHUNKS (T_TOK / SCAN_CHUNK)  // 1024
#define SCAN_GRID (SCAN_CHUNKS / 8)       // 128 blocks x 128 thr (8 chunks/blk)

__device__ __forceinline__ unsigned smem_u32(const void* p) {
    unsigned a;
    asm("{ .reg .u64 t; cvta.to.shared.u64 t, %1; cvt.u32.u64 %0, t; }"
        : "=r"(a) : "l"(p));
    return a;
}
__device__ __forceinline__ void cp16(unsigned dst, const void* src) {
    asm volatile("cp.async.cg.shared.global [%0], [%1], 16;"
                 :: "r"(dst), "l"(src) : "memory");
}
__device__ __forceinline__ void ldsm4(unsigned& r0, unsigned& r1,
                                      unsigned& r2, unsigned& r3, unsigned a) {
    asm volatile("ldmatrix.sync.aligned.m8n8.x4.shared.b16 {%0,%1,%2,%3}, [%4];"
                 : "=r"(r0), "=r"(r1), "=r"(r2), "=r"(r3) : "r"(a));
}

// ---------------------------------------------------------------------------
// GEMM tile body — round-5 config; epilogue writes fp16 gate
// ---------------------------------------------------------------------------
__device__ __forceinline__ void gemm_tile_body(
    int tile, const float* __restrict__ x,
    const float* __restrict__ gate_w, const float* __restrict__ gate_b,
    float* smemf)
{
    const int m0 = (tile >> 3) * GTM;
    const int n0 = (tile & 7) * GTN;

    const int tid = threadIdx.x;
    const int wid = tid >> 5;
    const int lane = tid & 31;
    const int wm = (wid & 3) * 32;
    const int wn = (wid >> 2) * 64;
    const int lq = lane >> 2;
    const int lr = lane & 3;

    const unsigned sbase = smem_u32(smemf);

    const int a_row = wm + (lane & 7) + ((lane >> 3) & 1) * 8;   // + mi*16
    const int a_kx  = (lane >> 4) * 4;
    const int b_row = wn + (lane & 7) + ((lane >> 4) & 1) * 8;   // + nip*16
    const int b_kx  = ((lane >> 3) & 1) * 4;

    auto cp_stage = [&](int s) {
        const int kc = s * GBK;
        const unsigned sA = sbase + (unsigned)(s % NPIPE) * STAGE_BYTES;
        const unsigned sB = sA + A_FLOATS * 4;
#pragma unroll
        for (int q = 0; q < 4; ++q) {
            const int j = tid + 256 * q;
            const int row = j >> 3;
            const int kg = j & 7;
            cp16(sA + row * (ROWSTRIDE * 4) + kg * 16,
                 &x[(size_t)(m0 + row) * DM + kc + kg * 4]);
            cp16(sB + row * (ROWSTRIDE * 4) + kg * 16,
                 &gate_w[(size_t)(n0 + row) * DM + kc + kg * 4]);
        }
        asm volatile("cp.async.commit_group;" ::: "memory");
    };

    float c[2][8][4];
#pragma unroll
    for (int mi = 0; mi < 2; ++mi)
#pragma unroll
        for (int ni = 0; ni < 8; ++ni)
#pragma unroll
            for (int r = 0; r < 4; ++r) c[mi][ni][r] = 0.f;

    cp_stage(0);
    cp_stage(1);

    for (int s = 0; s < GSTAGES; ++s) {
        asm volatile("cp.async.wait_group 1;" ::: "memory");
        __syncthreads();

        const unsigned stg = sbase + (unsigned)(s % NPIPE) * STAGE_BYTES;
        const unsigned aAddr0 = stg + (unsigned)((a_row)*ROWSTRIDE + a_kx) * 4u;
        const unsigned bAddr0 = stg + (unsigned)(A_FLOATS + (b_row)*ROWSTRIDE + b_kx) * 4u;

#pragma unroll
        for (int ks = 0; ks < 4; ++ks) {
            const int k0 = ks * 8;
            unsigned af[2][4];
#pragma unroll
            for (int mi = 0; mi < 2; ++mi)
                ldsm4(af[mi][0], af[mi][1], af[mi][2], af[mi][3],
                      aAddr0 + (unsigned)(mi * 16 * ROWSTRIDE + k0) * 4u);
            unsigned bf[8][2];
#pragma unroll
            for (int nip = 0; nip < 4; ++nip)
                ldsm4(bf[nip * 2][0], bf[nip * 2][1],
                      bf[nip * 2 + 1][0], bf[nip * 2 + 1][1],
                      bAddr0 + (unsigned)(nip * 16 * ROWSTRIDE + k0) * 4u);
#pragma unroll
            for (int mi = 0; mi < 2; ++mi)
#pragma unroll
                for (int ni = 0; ni < 8; ++ni) {
                    asm volatile(
                        "mma.sync.aligned.m16n8k8.row.col.f32.tf32.tf32.f32 "
                        "{%0,%1,%2,%3}, {%4,%5,%6,%7}, {%8,%9}, {%0,%1,%2,%3};"
                        : "+f"(c[mi][ni][0]), "+f"(c[mi][ni][1]),
                          "+f"(c[mi][ni][2]), "+f"(c[mi][ni][3])
                        : "r"(af[mi][0]), "r"(af[mi][1]),
                          "r"(af[mi][2]), "r"(af[mi][3]),
                          "r"(bf[ni][0]), "r"(bf[ni][1]));
                }
        }
        if (s + 2 < GSTAGES) cp_stage(s + 2);
    }

#pragma unroll
    for (int ni = 0; ni < 8; ++ni) {
        const int col = n0 + wn + ni * 8 + lr * 2;
        const float2 gb = *reinterpret_cast<const float2*>(&gate_b[col]);
#pragma unroll
        for (int mi = 0; mi < 2; ++mi) {
            const int row0 = m0 + wm + mi * 16 + lq;
#pragma unroll
            for (int h = 0; h < 2; ++h) {
                const int row = row0 + h * 8;
                float z0 = c[mi][ni][h * 2 + 0] + gb.x;
                float z1 = c[mi][ni][h * 2 + 1] + gb.y;
                const float o0 = z0 / (1.0f + __expf(-z0));
                const float o1 = z1 / (1.0f + __expf(-z1));
                *reinterpret_cast<__half2*>(&g_gate_h[(size_t)row * DM + col]) =
                    __floats2half2_rn(o0, o1);
            }
        }
    }
}

// ---------------------------------------------------------------------------
// K1: bx (blocks 0..255) + full GEMM (blocks 256..2303)
// ---------------------------------------------------------------------------
__global__ void __launch_bounds__(256, 2) k1_kernel(
    const float* __restrict__ x,
    const float* __restrict__ B_w, const float* __restrict__ B_b,
    const float* __restrict__ gate_w, const float* __restrict__ gate_b)
{
    extern __shared__ float smemf[];
    const int tid = threadIdx.x;

    if (blockIdx.x < BX_GRID) {
        float* Bw_s = smemf;
        for (int i = tid; i < (NS * DM) / 4; i += 256)
            reinterpret_cast<float4*>(Bw_s)[i] = reinterpret_cast<const float4*>(B_w)[i];
        __syncthreads();

        const int w = tid >> 5, lane = tid & 31;
        const int tbase = blockIdx.x * 128 + w * 16;

        for (int g = 0; g < 4; ++g) {
            const int t0 = tbase + g * 4;
            float acc[4][NS];
#pragma unroll
            for (int tt = 0; tt < 4; ++tt)
#pragma unroll
                for (int n = 0; n < NS; ++n) acc[tt][n] = 0.f;

#pragma unroll 2
            for (int c = 0; c < 8; ++c) {
                const int k0 = c * 128 + lane * 4;
                float4 xv[4];
#pragma unroll
                for (int tt = 0; tt < 4; ++tt)
                    xv[tt] = *reinterpret_cast<const float4*>(&x[(size_t)(t0 + tt) * DM + k0]);
#pragma unroll
                for (int n = 0; n < NS; ++n) {
                    const float4 bw = *reinterpret_cast<const float4*>(&Bw_s[n * DM + k0]);
#pragma unroll
                    for (int tt = 0; tt < 4; ++tt) {
                        acc[tt][n] = fmaf(xv[tt].x, bw.x, acc[tt][n]);
                        acc[tt][n] = fmaf(xv[tt].y, bw.y, acc[tt][n]);
                        acc[tt][n] = fmaf(xv[tt].z, bw.z, acc[tt][n]);
                        acc[tt][n] = fmaf(xv[tt].w, bw.w, acc[tt][n]);
                    }
                }
            }
#pragma unroll
            for (int tt = 0; tt < 4; ++tt) {
                float outv = 0.f;
#pragma unroll
                for (int n = 0; n < NS; ++n) {
                    float v = acc[tt][n];
                    v += __shfl_xor_sync(0xffffffffu, v, 16);
                    v += __shfl_xor_sync(0xffffffffu, v, 8);
                    v += __shfl_xor_sync(0xffffffffu, v, 4);
                    v += __shfl_xor_sync(0xffffffffu, v, 2);
                    v += __shfl_xor_sync(0xffffffffu, v, 1);
                    if (lane == n) outv = v;
                }
                if (lane < NS)
                    g_Bx[(size_t)(t0 + tt) * NS + lane] = outv + B_b[lane];
            }
        }
        return;
    }

    gemm_tile_body(blockIdx.x - BX_GRID, x, gate_w, gate_b, smemf);
}

// ---------------------------------------------------------------------------
// K2: standalone scan — warm=16, chunk=32, group-of-4 rolling Bx prefetch.
// 128 blocks x 128 threads; one chunk per 16-lane half-warp.
// ---------------------------------------------------------------------------
__global__ void __launch_bounds__(128) scan_kernel(const float* __restrict__ A)
{
    const int hw = threadIdx.x >> 4;               // half-warp 0..7
    const int chunk = blockIdx.x * 8 + hw;         // 0..1023
    const int i = threadIdx.x & 15;
    const int batch = chunk >> 7;                  // 128 chunks per batch
    const int cib = chunk & 127;
    const int t0 = cib * SCAN_CHUNK;
    const int ts = (cib == 0) ? 0 : (t0 - SCAN_WARM);
    const int nsteps = t0 + SCAN_CHUNK - ts;       // 32 or 48 (mult of 4)

    float a[NS];
#pragma unroll
    for (int j = 0; j < NS; ++j) a[j] = __ldg(&A[i * NS + j]);

    const float* bxp = g_Bx + (size_t)batch * SEQ * NS;
    float* stp = g_states + (size_t)batch * SEQ * NS;

    float buf[2][4];
#pragma unroll
    for (int u = 0; u < 4; ++u) buf[0][u] = bxp[(ts + u) * NS + i];

    float s = 0.f;
    const int ngroups = nsteps >> 2;
    for (int g = 0; g < ngroups; ++g) {
        const int cur = g & 1;
        if (g + 1 < ngroups) {
            const int tn = ts + (g + 1) * 4;
#pragma unroll
            for (int u = 0; u < 4; ++u)
                buf[cur ^ 1][u] = bxp[(tn + u) * NS + i];
        }
#pragma unroll
        for (int u = 0; u < 4; ++u) {
            const int t = ts + g * 4 + u;
            float sv[NS];
#pragma unroll
            for (int j = 0; j < NS; ++j) sv[j] = __shfl_sync(0xffffffffu, s, j, 16);
            float p0 = fmaf(a[0], sv[0], fmaf(a[1], sv[1], fmaf(a[2], sv[2], a[3] * sv[3])));
            float p1 = fmaf(a[4], sv[4], fmaf(a[5], sv[5], fmaf(a[6], sv[6], a[7] * sv[7])));
            float p2 = fmaf(a[8], sv[8], fmaf(a[9], sv[9], fmaf(a[10], sv[10], a[11] * sv[11])));
            float p3 = fmaf(a[12], sv[12], fmaf(a[13], sv[13], fmaf(a[14], sv[14], a[15] * sv[15])));
            s = tanhf(buf[cur][u] + ((p0 + p1) + (p2 + p3)));
            if (t >= t0) stp[t * NS + i] = s;
        }
    }
}

// ---------------------------------------------------------------------------
// K3: combine + LayerNorm — direct LDG (round-8 style), fp16 gate.
// ---------------------------------------------------------------------------
__global__ void __launch_bounds__(256) combine_ln_kernel(
    const float* __restrict__ x, const float* __restrict__ C_w,
    const float* __restrict__ C_b, const float* __restrict__ Dv,
    const float* __restrict__ ln_g, const float* __restrict__ ln_b,
    float* __restrict__ out)
{
    __shared__ float st_s[8][NS];
    __shared__ float r_s[8][DM];
    __shared__ float wsum[8][8], wsq[8][8];
    __shared__ float mu_s[8], rs_s[8];

    const int tid = threadIdx.x;
    const int tok0 = blockIdx.x * 8;
    const int e0 = tid * 4;

    if (tid < 128)
        st_s[tid >> 4][tid & 15] =
            g_states[(size_t)(tok0 + (tid >> 4)) * NS + (tid & 15)];

    float cw[4][NS];
#pragma unroll
    for (int j = 0; j < 4; ++j)
#pragma unroll
        for (int n4 = 0; n4 < 4; ++n4) {
            const float4 v = *reinterpret_cast<const float4*>(&C_w[(e0 + j) * NS + n4 * 4]);
            cw[j][n4 * 4 + 0] = v.x;
            cw[j][n4 * 4 + 1] = v.y;
            cw[j][n4 * 4 + 2] = v.z;
            cw[j][n4 * 4 + 3] = v.w;
        }
    const float4 cb4 = *reinterpret_cast<const float4*>(&C_b[e0]);
    const float4 dv4 = *reinterpret_cast<const float4*>(&Dv[e0]);
    const float4 lg4 = *reinterpret_cast<const float4*>(&ln_g[e0]);
    const float4 lb4 = *reinterpret_cast<const float4*>(&ln_b[e0]);
    __syncthreads();

    const int warp = tid >> 5, lane = tid & 31;
#pragma unroll 2
    for (int r = 0; r < 8; ++r) {
        const size_t t = (size_t)(tok0 + r);
        const float4 xv = *reinterpret_cast<const float4*>(&x[t * DM + e0]);
        const uint2 gu = *reinterpret_cast<const uint2*>(&g_gate_h[t * DM + e0]);
        const float2 g01 = __half22float2(*reinterpret_cast<const __half2*>(&gu.x));
        const float2 g23 = __half22float2(*reinterpret_cast<const __half2*>(&gu.y));

        float so[4] = {cb4.x, cb4.y, cb4.z, cb4.w};
#pragma unroll
        for (int n = 0; n < NS; ++n) {
            const float st = st_s[r][n];
            so[0] = fmaf(st, cw[0][n], so[0]);
            so[1] = fmaf(st, cw[1][n], so[1]);
            so[2] = fmaf(st, cw[2][n], so[2]);
            so[3] = fmaf(st, cw[3][n], so[3]);
        }
        so[0] = fmaf(dv4.x, xv.x, so[0]);
        so[1] = fmaf(dv4.y, xv.y, so[1]);
        so[2] = fmaf(dv4.z, xv.z, so[2]);
        so[3] = fmaf(dv4.w, xv.w, so[3]);

        float4 rr;
        rr.x = fmaf(g01.x, so[0] - xv.x, xv.x) + xv.x;
        rr.y = fmaf(g01.y, so[1] - xv.y, xv.y) + xv.y;
        rr.z = fmaf(g23.x, so[2] - xv.z, xv.z) + xv.z;
        rr.w = fmaf(g23.y, so[3] - xv.w, xv.w) + xv.w;
        *reinterpret_cast<float4*>(&r_s[r][e0]) = rr;

        float ps = (rr.x + rr.y) + (rr.z + rr.w);
        float pq = fmaf(rr.x, rr.x, rr.y * rr.y) + fmaf(rr.z, rr.z, rr.w * rr.w);
#pragma unroll
        for (int off = 16; off; off >>= 1) {
            ps += __shfl_xor_sync(0xffffffffu, ps, off);
            pq += __shfl_xor_sync(0xffffffffu, pq, off);
        }
        if (lane == 0) { wsum[r][warp] = ps; wsq[r][warp] = pq; }
    }
    __syncthreads();

    if (tid < 8) {
        float s = 0.f, s2 = 0.f;
#pragma unroll
        for (int w = 0; w < 8; ++w) { s += wsum[tid][w]; s2 += wsq[tid][w]; }
        const float mu = s * (1.0f / DM);
        float var = s2 * (1.0f / DM) - mu * mu;
        var = fmaxf(var, 0.f);
        mu_s[tid] = mu;
        rs_s[tid] = rsqrtf(var + 1e-5f);
    }
    __syncthreads();

#pragma unroll 2
    for (int r = 0; r < 8; ++r) {
        const size_t t = (size_t)(tok0 + r);
        const float mu = mu_s[r], rs = rs_s[r];
        const float4 rr = *reinterpret_cast<const float4*>(&r_s[r][e0]);
        float4 o;
        o.x = (rr.x - mu) * rs * lg4.x + lb4.x;
        o.y = (rr.y - mu) * rs * lg4.y + lb4.y;
        o.z = (rr.z - mu) * rs * lg4.z + lb4.z;
        o.w = (rr.w - mu) * rs * lg4.w + lb4.w;
        *reinterpret_cast<float4*>(&out[t * DM + e0]) = o;
    }
}

// ---------------------------------------------------------------------------
extern "C" void kernel_launch(void* const* d_in, const int* in_sizes, int n_in,
                              void* d_out, int out_size)
{
    const float* x      = (const float*)d_in[0];
    const float* A      = (const float*)d_in[1];
    const float* B_w    = (const float*)d_in[2];
    const float* B_b    = (const float*)d_in[3];
    const float* C_w    = (const float*)d_in[4];
    const float* C_b    = (const float*)d_in[5];
    const float* Dv     = (const float*)d_in[6];
    const float* gate_w = (const float*)d_in[7];
    const float* gate_b = (const float*)d_in[8];
    const float* ln_g   = (const float*)d_in[9];
    const float* ln_b   = (const float*)d_in[10];
    float* out = (float*)d_out;

    cudaFuncSetAttribute(k1_kernel, cudaFuncAttributeMaxDynamicSharedMemorySize,
                         GEMM_SMEM);

    k1_kernel<<<BX_GRID + GEMM_BLOCKS, 256, GEMM_SMEM>>>(x, B_w, B_b, gate_w, gate_b);
    scan_kernel<<<SCAN_GRID, 128>>>(A);
    combine_ln_kernel<<<T_TOK / 8, 256>>>(x, C_w, C_b, Dv, ln_g, ln_b, out);
}

// round 14
// speedup vs baseline: 1.0761x; 1.0111x over previous
#include <cuda_runtime.h>
#include <cuda_fp16.h>
#include <math.h>

// ---------------------------------------------------------------------------
// SimplifiedSSMLayer: B=8, S=4096, D_MODEL=1024, D_STATE=16
// Round 14:
//   K1 = bx + GEMM (round-13 verbatim, fp16 gate)
//   K2 = scan (round-13 verbatim)
//   K3 = combine+LN with ALL-ROWS-UPFRONT register loads (MLP=16/thread)
// ---------------------------------------------------------------------------

#define BATCH   8
#define SEQ     4096
#define DM      1024
#define NS      16
#define T_TOK   (BATCH*SEQ)          // 32768

__device__ float  g_Bx[T_TOK * NS];              // 2 MB
__device__ float  g_states[T_TOK * NS];          // 2 MB
__device__ __half g_gate_h[(size_t)T_TOK * DM];  // 64 MB

#define BX_GRID 256

#define GTM 128
#define GTN 128
#define GBK 32
#define GSTAGES (DM / GBK)                // 32
#define GEMM_BLOCKS 2048

#define ROWSTRIDE 36                      // floats; ldsm conflict-free
#define A_FLOATS (GTM * ROWSTRIDE)        // 4608
#define STAGE_FLOATS (2 * A_FLOATS)       // 9216
#define STAGE_BYTES (STAGE_FLOATS * 4)    // 36864
#define NPIPE 3
#define GEMM_SMEM (NPIPE * STAGE_BYTES)   // 110592 -> 2 CTAs/SM

#define SCAN_CHUNK 32
#define SCAN_WARM  16
#define SCAN_CHUNKS (T_TOK / SCAN_CHUNK)  // 1024
#define SCAN_GRID (SCAN_CHUNKS / 8)       // 128 blocks

__device__ __forceinline__ unsigned smem_u32(const void* p) {
    unsigned a;
    asm("{ .reg .u64 t; cvta.to.shared.u64 t, %1; cvt.u32.u64 %0, t; }"
        : "=r"(a) : "l"(p));
    return a;
}
__device__ __forceinline__ void cp16(unsigned dst, const void* src) {
    asm volatile("cp.async.cg.shared.global [%0], [%1], 16;"
                 :: "r"(dst), "l"(src) : "memory");
}
__device__ __forceinline__ void ldsm4(unsigned& r0, unsigned& r1,
                                      unsigned& r2, unsigned& r3, unsigned a) {
    asm volatile("ldmatrix.sync.aligned.m8n8.x4.shared.b16 {%0,%1,%2,%3}, [%4];"
                 : "=r"(r0), "=r"(r1), "=r"(r2), "=r"(r3) : "r"(a));
}

// ---------------------------------------------------------------------------
// GEMM tile body — round-5 config; epilogue writes fp16 gate
// ---------------------------------------------------------------------------
__device__ __forceinline__ void gemm_tile_body(
    int tile, const float* __restrict__ x,
    const float* __restrict__ gate_w, const float* __restrict__ gate_b,
    float* smemf)
{
    const int m0 = (tile >> 3) * GTM;
    const int n0 = (tile & 7) * GTN;

    const int tid = threadIdx.x;
    const int wid = tid >> 5;
    const int lane = tid & 31;
    const int wm = (wid & 3) * 32;
    const int wn = (wid >> 2) * 64;
    const int lq = lane >> 2;
    const int lr = lane & 3;

    const unsigned sbase = smem_u32(smemf);

    const int a_row = wm + (lane & 7) + ((lane >> 3) & 1) * 8;   // + mi*16
    const int a_kx  = (lane >> 4) * 4;
    const int b_row = wn + (lane & 7) + ((lane >> 4) & 1) * 8;   // + nip*16
    const int b_kx  = ((lane >> 3) & 1) * 4;

    auto cp_stage = [&](int s) {
        const int kc = s * GBK;
        const unsigned sA = sbase + (unsigned)(s % NPIPE) * STAGE_BYTES;
        const unsigned sB = sA + A_FLOATS * 4;
#pragma unroll
        for (int q = 0; q < 4; ++q) {
            const int j = tid + 256 * q;
            const int row = j >> 3;
            const int kg = j & 7;
            cp16(sA + row * (ROWSTRIDE * 4) + kg * 16,
                 &x[(size_t)(m0 + row) * DM + kc + kg * 4]);
            cp16(sB + row * (ROWSTRIDE * 4) + kg * 16,
                 &gate_w[(size_t)(n0 + row) * DM + kc + kg * 4]);
        }
        asm volatile("cp.async.commit_group;" ::: "memory");
    };

    float c[2][8][4];
#pragma unroll
    for (int mi = 0; mi < 2; ++mi)
#pragma unroll
        for (int ni = 0; ni < 8; ++ni)
#pragma unroll
            for (int r = 0; r < 4; ++r) c[mi][ni][r] = 0.f;

    cp_stage(0);
    cp_stage(1);

    for (int s = 0; s < GSTAGES; ++s) {
        asm volatile("cp.async.wait_group 1;" ::: "memory");
        __syncthreads();

        const unsigned stg = sbase + (unsigned)(s % NPIPE) * STAGE_BYTES;
        const unsigned aAddr0 = stg + (unsigned)((a_row)*ROWSTRIDE + a_kx) * 4u;
        const unsigned bAddr0 = stg + (unsigned)(A_FLOATS + (b_row)*ROWSTRIDE + b_kx) * 4u;

#pragma unroll
        for (int ks = 0; ks < 4; ++ks) {
            const int k0 = ks * 8;
            unsigned af[2][4];
#pragma unroll
            for (int mi = 0; mi < 2; ++mi)
                ldsm4(af[mi][0], af[mi][1], af[mi][2], af[mi][3],
                      aAddr0 + (unsigned)(mi * 16 * ROWSTRIDE + k0) * 4u);
            unsigned bf[8][2];
#pragma unroll
            for (int nip = 0; nip < 4; ++nip)
                ldsm4(bf[nip * 2][0], bf[nip * 2][1],
                      bf[nip * 2 + 1][0], bf[nip * 2 + 1][1],
                      bAddr0 + (unsigned)(nip * 16 * ROWSTRIDE + k0) * 4u);
#pragma unroll
            for (int mi = 0; mi < 2; ++mi)
#pragma unroll
                for (int ni = 0; ni < 8; ++ni) {
                    asm volatile(
                        "mma.sync.aligned.m16n8k8.row.col.f32.tf32.tf32.f32 "
                        "{%0,%1,%2,%3}, {%4,%5,%6,%7}, {%8,%9}, {%0,%1,%2,%3};"
                        : "+f"(c[mi][ni][0]), "+f"(c[mi][ni][1]),
                          "+f"(c[mi][ni][2]), "+f"(c[mi][ni][3])
                        : "r"(af[mi][0]), "r"(af[mi][1]),
                          "r"(af[mi][2]), "r"(af[mi][3]),
                          "r"(bf[ni][0]), "r"(bf[ni][1]));
                }
        }
        if (s + 2 < GSTAGES) cp_stage(s + 2);
    }

#pragma unroll
    for (int ni = 0; ni < 8; ++ni) {
        const int col = n0 + wn + ni * 8 + lr * 2;
        const float2 gb = *reinterpret_cast<const float2*>(&gate_b[col]);
#pragma unroll
        for (int mi = 0; mi < 2; ++mi) {
            const int row0 = m0 + wm + mi * 16 + lq;
#pragma unroll
            for (int h = 0; h < 2; ++h) {
                const int row = row0 + h * 8;
                float z0 = c[mi][ni][h * 2 + 0] + gb.x;
                float z1 = c[mi][ni][h * 2 + 1] + gb.y;
                const float o0 = z0 / (1.0f + __expf(-z0));
                const float o1 = z1 / (1.0f + __expf(-z1));
                *reinterpret_cast<__half2*>(&g_gate_h[(size_t)row * DM + col]) =
                    __floats2half2_rn(o0, o1);
            }
        }
    }
}

// ---------------------------------------------------------------------------
// K1: bx (blocks 0..255) + full GEMM (blocks 256..2303)
// ---------------------------------------------------------------------------
__global__ void __launch_bounds__(256, 2) k1_kernel(
    const float* __restrict__ x,
    const float* __restrict__ B_w, const float* __restrict__ B_b,
    const float* __restrict__ gate_w, const float* __restrict__ gate_b)
{
    extern __shared__ float smemf[];
    const int tid = threadIdx.x;

    if (blockIdx.x < BX_GRID) {
        float* Bw_s = smemf;
        for (int i = tid; i < (NS * DM) / 4; i += 256)
            reinterpret_cast<float4*>(Bw_s)[i] = reinterpret_cast<const float4*>(B_w)[i];
        __syncthreads();

        const int w = tid >> 5, lane = tid & 31;
        const int tbase = blockIdx.x * 128 + w * 16;

        for (int g = 0; g < 4; ++g) {
            const int t0 = tbase + g * 4;
            float acc[4][NS];
#pragma unroll
            for (int tt = 0; tt < 4; ++tt)
#pragma unroll
                for (int n = 0; n < NS; ++n) acc[tt][n] = 0.f;

#pragma unroll 2
            for (int c = 0; c < 8; ++c) {
                const int k0 = c * 128 + lane * 4;
                float4 xv[4];
#pragma unroll
                for (int tt = 0; tt < 4; ++tt)
                    xv[tt] = *reinterpret_cast<const float4*>(&x[(size_t)(t0 + tt) * DM + k0]);
#pragma unroll
                for (int n = 0; n < NS; ++n) {
                    const float4 bw = *reinterpret_cast<const float4*>(&Bw_s[n * DM + k0]);
#pragma unroll
                    for (int tt = 0; tt < 4; ++tt) {
                        acc[tt][n] = fmaf(xv[tt].x, bw.x, acc[tt][n]);
                        acc[tt][n] = fmaf(xv[tt].y, bw.y, acc[tt][n]);
                        acc[tt][n] = fmaf(xv[tt].z, bw.z, acc[tt][n]);
                        acc[tt][n] = fmaf(xv[tt].w, bw.w, acc[tt][n]);
                    }
                }
            }
#pragma unroll
            for (int tt = 0; tt < 4; ++tt) {
                float outv = 0.f;
#pragma unroll
                for (int n = 0; n < NS; ++n) {
                    float v = acc[tt][n];
                    v += __shfl_xor_sync(0xffffffffu, v, 16);
                    v += __shfl_xor_sync(0xffffffffu, v, 8);
                    v += __shfl_xor_sync(0xffffffffu, v, 4);
                    v += __shfl_xor_sync(0xffffffffu, v, 2);
                    v += __shfl_xor_sync(0xffffffffu, v, 1);
                    if (lane == n) outv = v;
                }
                if (lane < NS)
                    g_Bx[(size_t)(t0 + tt) * NS + lane] = outv + B_b[lane];
            }
        }
        return;
    }

    gemm_tile_body(blockIdx.x - BX_GRID, x, gate_w, gate_b, smemf);
}

// ---------------------------------------------------------------------------
// K2: standalone scan — warm=16, chunk=32, group-of-4 rolling Bx prefetch.
// ---------------------------------------------------------------------------
__global__ void __launch_bounds__(128) scan_kernel(const float* __restrict__ A)
{
    const int hw = threadIdx.x >> 4;
    const int chunk = blockIdx.x * 8 + hw;         // 0..1023
    const int i = threadIdx.x & 15;
    const int batch = chunk >> 7;
    const int cib = chunk & 127;
    const int t0 = cib * SCAN_CHUNK;
    const int ts = (cib == 0) ? 0 : (t0 - SCAN_WARM);
    const int nsteps = t0 + SCAN_CHUNK - ts;

    float a[NS];
#pragma unroll
    for (int j = 0; j < NS; ++j) a[j] = __ldg(&A[i * NS + j]);

    const float* bxp = g_Bx + (size_t)batch * SEQ * NS;
    float* stp = g_states + (size_t)batch * SEQ * NS;

    float buf[2][4];
#pragma unroll
    for (int u = 0; u < 4; ++u) buf[0][u] = bxp[(ts + u) * NS + i];

    float s = 0.f;
    const int ngroups = nsteps >> 2;
    for (int g = 0; g < ngroups; ++g) {
        const int cur = g & 1;
        if (g + 1 < ngroups) {
            const int tn = ts + (g + 1) * 4;
#pragma unroll
            for (int u = 0; u < 4; ++u)
                buf[cur ^ 1][u] = bxp[(tn + u) * NS + i];
        }
#pragma unroll
        for (int u = 0; u < 4; ++u) {
            const int t = ts + g * 4 + u;
            float sv[NS];
#pragma unroll
            for (int j = 0; j < NS; ++j) sv[j] = __shfl_sync(0xffffffffu, s, j, 16);
            float p0 = fmaf(a[0], sv[0], fmaf(a[1], sv[1], fmaf(a[2], sv[2], a[3] * sv[3])));
            float p1 = fmaf(a[4], sv[4], fmaf(a[5], sv[5], fmaf(a[6], sv[6], a[7] * sv[7])));
            float p2 = fmaf(a[8], sv[8], fmaf(a[9], sv[9], fmaf(a[10], sv[10], a[11] * sv[11])));
            float p3 = fmaf(a[12], sv[12], fmaf(a[13], sv[13], fmaf(a[14], sv[14], a[15] * sv[15])));
            s = tanhf(buf[cur][u] + ((p0 + p1) + (p2 + p3)));
            if (t >= t0) stp[t * NS + i] = s;
        }
    }
}

// ---------------------------------------------------------------------------
// K3: combine + LayerNorm — all 8 rows' x/gate loaded upfront (MLP=16).
// ---------------------------------------------------------------------------
__global__ void __launch_bounds__(256) combine_ln_kernel(
    const float* __restrict__ x, const float* __restrict__ C_w,
    const float* __restrict__ C_b, const float* __restrict__ Dv,
    const float* __restrict__ ln_g, const float* __restrict__ ln_b,
    float* __restrict__ out)
{
    __shared__ float st_s[8][NS];
    __shared__ float r_s[8][DM];
    __shared__ float wsum[8][8], wsq[8][8];
    __shared__ float mu_s[8], rs_s[8];

    const int tid = threadIdx.x;
    const int tok0 = blockIdx.x * 8;
    const int e0 = tid * 4;

    // ---- upfront loads: all 8 rows of x and gate (16 independent LDGs) ----
    float4 xv[8];
    uint2  gu[8];
#pragma unroll
    for (int r = 0; r < 8; ++r) {
        const size_t t = (size_t)(tok0 + r);
        xv[r] = *reinterpret_cast<const float4*>(&x[t * DM + e0]);
        gu[r] = *reinterpret_cast<const uint2*>(&g_gate_h[t * DM + e0]);
    }

    if (tid < 128)
        st_s[tid >> 4][tid & 15] =
            g_states[(size_t)(tok0 + (tid >> 4)) * NS + (tid & 15)];

    float cw[4][NS];
#pragma unroll
    for (int j = 0; j < 4; ++j)
#pragma unroll
        for (int n4 = 0; n4 < 4; ++n4) {
            const float4 v = *reinterpret_cast<const float4*>(&C_w[(e0 + j) * NS + n4 * 4]);
            cw[j][n4 * 4 + 0] = v.x;
            cw[j][n4 * 4 + 1] = v.y;
            cw[j][n4 * 4 + 2] = v.z;
            cw[j][n4 * 4 + 3] = v.w;
        }
    const float4 cb4 = *reinterpret_cast<const float4*>(&C_b[e0]);
    const float4 dv4 = *reinterpret_cast<const float4*>(&Dv[e0]);
    __syncthreads();

    const int warp = tid >> 5, lane = tid & 31;
#pragma unroll
    for (int r = 0; r < 8; ++r) {
        const float2 g01 = __half22float2(*reinterpret_cast<const __half2*>(&gu[r].x));
        const float2 g23 = __half22float2(*reinterpret_cast<const __half2*>(&gu[r].y));

        float so[4] = {cb4.x, cb4.y, cb4.z, cb4.w};
#pragma unroll
        for (int n = 0; n < NS; ++n) {
            const float st = st_s[r][n];
            so[0] = fmaf(st, cw[0][n], so[0]);
            so[1] = fmaf(st, cw[1][n], so[1]);
            so[2] = fmaf(st, cw[2][n], so[2]);
            so[3] = fmaf(st, cw[3][n], so[3]);
        }
        so[0] = fmaf(dv4.x, xv[r].x, so[0]);
        so[1] = fmaf(dv4.y, xv[r].y, so[1]);
        so[2] = fmaf(dv4.z, xv[r].z, so[2]);
        so[3] = fmaf(dv4.w, xv[r].w, so[3]);

        float4 rr;
        rr.x = fmaf(g01.x, so[0] - xv[r].x, xv[r].x) + xv[r].x;
        rr.y = fmaf(g01.y, so[1] - xv[r].y, xv[r].y) + xv[r].y;
        rr.z = fmaf(g23.x, so[2] - xv[r].z, xv[r].z) + xv[r].z;
        rr.w = fmaf(g23.y, so[3] - xv[r].w, xv[r].w) + xv[r].w;
        *reinterpret_cast<float4*>(&r_s[r][e0]) = rr;

        float ps = (rr.x + rr.y) + (rr.z + rr.w);
        float pq = fmaf(rr.x, rr.x, rr.y * rr.y) + fmaf(rr.z, rr.z, rr.w * rr.w);
#pragma unroll
        for (int off = 16; off; off >>= 1) {
            ps += __shfl_xor_sync(0xffffffffu, ps, off);
            pq += __shfl_xor_sync(0xffffffffu, pq, off);
        }
        if (lane == 0) { wsum[r][warp] = ps; wsq[r][warp] = pq; }
    }
    __syncthreads();

    if (tid < 8) {
        float s = 0.f, s2 = 0.f;
#pragma unroll
        for (int w = 0; w < 8; ++w) { s += wsum[tid][w]; s2 += wsq[tid][w]; }
        const float mu = s * (1.0f / DM);
        float var = s2 * (1.0f / DM) - mu * mu;
        var = fmaxf(var, 0.f);
        mu_s[tid] = mu;
        rs_s[tid] = rsqrtf(var + 1e-5f);
    }
    __syncthreads();

    const float4 lg4 = *reinterpret_cast<const float4*>(&ln_g[e0]);
    const float4 lb4 = *reinterpret_cast<const float4*>(&ln_b[e0]);
#pragma unroll
    for (int r = 0; r < 8; ++r) {
        const size_t t = (size_t)(tok0 + r);
        const float mu = mu_s[r], rs = rs_s[r];
        const float4 rr = *reinterpret_cast<const float4*>(&r_s[r][e0]);
        float4 o;
        o.x = (rr.x - mu) * rs * lg4.x + lb4.x;
        o.y = (rr.y - mu) * rs * lg4.y + lb4.y;
        o.z = (rr.z - mu) * rs * lg4.z + lb4.z;
        o.w = (rr.w - mu) * rs * lg4.w + lb4.w;
        *reinterpret_cast<float4*>(&out[t * DM + e0]) = o;
    }
}

// ---------------------------------------------------------------------------
extern "C" void kernel_launch(void* const* d_in, const int* in_sizes, int n_in,
                              void* d_out, int out_size)
{
    const float* x      = (const float*)d_in[0];
    const float* A      = (const float*)d_in[1];
    const float* B_w    = (const float*)d_in[2];
    const float* B_b    = (const float*)d_in[3];
    const float* C_w    = (const float*)d_in[4];
    const float* C_b    = (const float*)d_in[5];
    const float* Dv     = (const float*)d_in[6];
    const float* gate_w = (const float*)d_in[7];
    const float* gate_b = (const float*)d_in[8];
    const float* ln_g   = (const float*)d_in[9];
    const float* ln_b   = (const float*)d_in[10];
    float* out = (float*)d_out;

    cudaFuncSetAttribute(k1_kernel, cudaFuncAttributeMaxDynamicSharedMemorySize,
                         GEMM_SMEM);

    k1_kernel<<<BX_GRID + GEMM_BLOCKS, 256, GEMM_SMEM>>>(x, B_w, B_b, gate_w, gate_b);
    scan_kernel<<<SCAN_GRID, 128>>>(A);
    combine_ln_kernel<<<T_TOK / 8, 256>>>(x, C_w, C_b, Dv, ln_g, ln_b, out);
}

// round 15
// speedup vs baseline: 1.3110x; 1.2182x over previous
#include <cuda_runtime.h>
#include <cuda_fp16.h>
#include <math.h>

// ---------------------------------------------------------------------------
// SimplifiedSSMLayer: B=8, S=4096, D_MODEL=1024, D_STATE=16
// Round 15: fp16 gate GEMM (m16n8k16, 2x tensor throughput, same 10-bit
// mantissa as tf32).
//   K0 = bx blocks (also convert x->fp16 in-register) + gate_w->fp16 blocks
//   K1 = scan (128 blocks) + fp16 GEMM (2048 tiles)
//   K3 = combine+LN (round-14 verbatim)
// ---------------------------------------------------------------------------

#define BATCH   8
#define SEQ     4096
#define DM      1024
#define NS      16
#define T_TOK   (BATCH*SEQ)          // 32768

__device__ float  g_Bx[T_TOK * NS];              // 2 MB
__device__ float  g_states[T_TOK * NS];          // 2 MB
__device__ __half g_gate_h[(size_t)T_TOK * DM];  // 64 MB
__device__ __half g_x_h[(size_t)T_TOK * DM];     // 64 MB
__device__ __half g_gw_h[DM * DM];               // 2 MB

#define BX_GRID 256
#define GWCVT_GRID 4

#define GTM 128
#define GTN 128
#define GBK 32
#define GSTAGES (DM / GBK)                // 32
#define GEMM_BLOCKS 2048

#define ROWH 40                           // halves per row (80B, conflict-free)
#define A_HALVES (GTM * ROWH)             // 5120
#define STAGE_HALVES (2 * A_HALVES)       // 10240
#define STAGE_BYTES (STAGE_HALVES * 2)    // 20480
#define NPIPE 3
#define GEMM_SMEM (NPIPE * STAGE_BYTES)   // 61440

#define SCAN_CHUNK 32
#define SCAN_WARM  16
#define SCAN_GRID 128                     // 8 chunks per block (half-warps)

__device__ __forceinline__ unsigned smem_u32(const void* p) {
    unsigned a;
    asm("{ .reg .u64 t; cvta.to.shared.u64 t, %1; cvt.u32.u64 %0, t; }"
        : "=r"(a) : "l"(p));
    return a;
}
__device__ __forceinline__ void cp16(unsigned dst, const void* src) {
    asm volatile("cp.async.cg.shared.global [%0], [%1], 16;"
                 :: "r"(dst), "l"(src) : "memory");
}
__device__ __forceinline__ void ldsm4(unsigned& r0, unsigned& r1,
                                      unsigned& r2, unsigned& r3, unsigned a) {
    asm volatile("ldmatrix.sync.aligned.m8n8.x4.shared.b16 {%0,%1,%2,%3}, [%4];"
                 : "=r"(r0), "=r"(r1), "=r"(r2), "=r"(r3) : "r"(a));
}

// ---------------------------------------------------------------------------
// K0: bx + x->fp16 (blocks 0..255) and gate_w->fp16 (blocks 256..259)
// ---------------------------------------------------------------------------
__global__ void __launch_bounds__(256) prep_kernel(
    const float* __restrict__ x,
    const float* __restrict__ B_w, const float* __restrict__ B_b,
    const float* __restrict__ gate_w)
{
    extern __shared__ float smemf[];
    const int tid = threadIdx.x;

    if (blockIdx.x >= BX_GRID) {
        // gate_w -> fp16: 4 blocks x 256 thr x 256 float4
        const int b = blockIdx.x - BX_GRID;
        const int base = b * 65536;
#pragma unroll 4
        for (int q = 0; q < 256; ++q) {
            const int idx = base + q * 256 + tid;      // float4 index
            const float4 v = *reinterpret_cast<const float4*>(&gate_w[(size_t)idx * 4]);
            uint2 h;
            *reinterpret_cast<__half2*>(&h.x) = __floats2half2_rn(v.x, v.y);
            *reinterpret_cast<__half2*>(&h.y) = __floats2half2_rn(v.z, v.w);
            *reinterpret_cast<uint2*>(&g_gw_h[(size_t)idx * 4]) = h;
        }
        return;
    }

    // bx + x conversion
    float* Bw_s = smemf;
    for (int i = tid; i < (NS * DM) / 4; i += 256)
        reinterpret_cast<float4*>(Bw_s)[i] = reinterpret_cast<const float4*>(B_w)[i];
    __syncthreads();

    const int w = tid >> 5, lane = tid & 31;
    const int tbase = blockIdx.x * 128 + w * 16;

    for (int g = 0; g < 4; ++g) {
        const int t0 = tbase + g * 4;
        float acc[4][NS];
#pragma unroll
        for (int tt = 0; tt < 4; ++tt)
#pragma unroll
            for (int n = 0; n < NS; ++n) acc[tt][n] = 0.f;

#pragma unroll 2
        for (int c = 0; c < 8; ++c) {
            const int k0 = c * 128 + lane * 4;
            float4 xv[4];
#pragma unroll
            for (int tt = 0; tt < 4; ++tt) {
                xv[tt] = *reinterpret_cast<const float4*>(&x[(size_t)(t0 + tt) * DM + k0]);
                uint2 h;
                *reinterpret_cast<__half2*>(&h.x) = __floats2half2_rn(xv[tt].x, xv[tt].y);
                *reinterpret_cast<__half2*>(&h.y) = __floats2half2_rn(xv[tt].z, xv[tt].w);
                *reinterpret_cast<uint2*>(&g_x_h[(size_t)(t0 + tt) * DM + k0]) = h;
            }
#pragma unroll
            for (int n = 0; n < NS; ++n) {
                const float4 bw = *reinterpret_cast<const float4*>(&Bw_s[n * DM + k0]);
#pragma unroll
                for (int tt = 0; tt < 4; ++tt) {
                    acc[tt][n] = fmaf(xv[tt].x, bw.x, acc[tt][n]);
                    acc[tt][n] = fmaf(xv[tt].y, bw.y, acc[tt][n]);
                    acc[tt][n] = fmaf(xv[tt].z, bw.z, acc[tt][n]);
                    acc[tt][n] = fmaf(xv[tt].w, bw.w, acc[tt][n]);
                }
            }
        }
#pragma unroll
        for (int tt = 0; tt < 4; ++tt) {
            float outv = 0.f;
#pragma unroll
            for (int n = 0; n < NS; ++n) {
                float v = acc[tt][n];
                v += __shfl_xor_sync(0xffffffffu, v, 16);
                v += __shfl_xor_sync(0xffffffffu, v, 8);
                v += __shfl_xor_sync(0xffffffffu, v, 4);
                v += __shfl_xor_sync(0xffffffffu, v, 2);
                v += __shfl_xor_sync(0xffffffffu, v, 1);
                if (lane == n) outv = v;
            }
            if (lane < NS)
                g_Bx[(size_t)(t0 + tt) * NS + lane] = outv + B_b[lane];
        }
    }
}

// ---------------------------------------------------------------------------
// fp16 GEMM tile body: 128x128 tile, BK=32, 3-stage cp.async, m16n8k16.
// ---------------------------------------------------------------------------
__device__ __forceinline__ void gemm_tile_body(
    int tile, const float* __restrict__ gate_b, char* smem)
{
    const int m0 = (tile >> 3) * GTM;
    const int n0 = (tile & 7) * GTN;

    const int tid = threadIdx.x;
    const int wid = tid >> 5;
    const int lane = tid & 31;
    const int wm = (wid & 3) * 32;
    const int wn = (wid >> 2) * 64;
    const int lq = lane >> 2;
    const int lr = lane & 3;

    const unsigned sbase = smem_u32(smem);

    // ldmatrix per-thread source rows (halves)
    const int a_row = wm + (lane & 7) + ((lane >> 3) & 1) * 8;   // + mi*16
    const int a_kxh = (lane >> 4) * 8;
    const int b_row = wn + (lane & 7) + ((lane >> 4) & 1) * 8;   // + nip*16
    const int b_kxh = ((lane >> 3) & 1) * 8;

    auto cp_stage = [&](int s) {
        const int kc = s * GBK;
        const unsigned sA = sbase + (unsigned)(s % NPIPE) * STAGE_BYTES;
        const unsigned sB = sA + A_HALVES * 2;
#pragma unroll
        for (int q = 0; q < 2; ++q) {
            const int j = tid + 256 * q;   // 0..511
            const int row = j >> 2;
            const int kg = j & 3;
            cp16(sA + row * (ROWH * 2) + kg * 16,
                 &g_x_h[(size_t)(m0 + row) * DM + kc + kg * 8]);
            cp16(sB + row * (ROWH * 2) + kg * 16,
                 &g_gw_h[(size_t)(n0 + row) * DM + kc + kg * 8]);
        }
        asm volatile("cp.async.commit_group;" ::: "memory");
    };

    float c[2][8][4];
#pragma unroll
    for (int mi = 0; mi < 2; ++mi)
#pragma unroll
        for (int ni = 0; ni < 8; ++ni)
#pragma unroll
            for (int r = 0; r < 4; ++r) c[mi][ni][r] = 0.f;

    cp_stage(0);
    cp_stage(1);

    for (int s = 0; s < GSTAGES; ++s) {
        asm volatile("cp.async.wait_group 1;" ::: "memory");
        __syncthreads();

        const unsigned stg = sbase + (unsigned)(s % NPIPE) * STAGE_BYTES;
        const unsigned aAddr0 = stg + (unsigned)(a_row * ROWH + a_kxh) * 2u;
        const unsigned bAddr0 = stg + (unsigned)(A_HALVES + b_row * ROWH + b_kxh) * 2u;

#pragma unroll
        for (int ks = 0; ks < 2; ++ks) {
            const int k0h = ks * 16;
            unsigned af[2][4];
#pragma unroll
            for (int mi = 0; mi < 2; ++mi)
                ldsm4(af[mi][0], af[mi][1], af[mi][2], af[mi][3],
                      aAddr0 + (unsigned)(mi * 16 * ROWH + k0h) * 2u);
            unsigned bf[8][2];
#pragma unroll
            for (int nip = 0; nip < 4; ++nip)
                ldsm4(bf[nip * 2][0], bf[nip * 2][1],
                      bf[nip * 2 + 1][0], bf[nip * 2 + 1][1],
                      bAddr0 + (unsigned)(nip * 16 * ROWH + k0h) * 2u);
#pragma unroll
            for (int mi = 0; mi < 2; ++mi)
#pragma unroll
                for (int ni = 0; ni < 8; ++ni) {
                    asm volatile(
                        "mma.sync.aligned.m16n8k16.row.col.f32.f16.f16.f32 "
                        "{%0,%1,%2,%3}, {%4,%5,%6,%7}, {%8,%9}, {%0,%1,%2,%3};"
                        : "+f"(c[mi][ni][0]), "+f"(c[mi][ni][1]),
                          "+f"(c[mi][ni][2]), "+f"(c[mi][ni][3])
                        : "r"(af[mi][0]), "r"(af[mi][1]),
                          "r"(af[mi][2]), "r"(af[mi][3]),
                          "r"(bf[ni][0]), "r"(bf[ni][1]));
                }
        }
        if (s + 2 < GSTAGES) cp_stage(s + 2);
    }

    // epilogue: silu(acc + gate_b) -> fp16 gate
#pragma unroll
    for (int ni = 0; ni < 8; ++ni) {
        const int col = n0 + wn + ni * 8 + lr * 2;
        const float2 gb = *reinterpret_cast<const float2*>(&gate_b[col]);
#pragma unroll
        for (int mi = 0; mi < 2; ++mi) {
            const int row0 = m0 + wm + mi * 16 + lq;
#pragma unroll
            for (int h = 0; h < 2; ++h) {
                const int row = row0 + h * 8;
                float z0 = c[mi][ni][h * 2 + 0] + gb.x;
                float z1 = c[mi][ni][h * 2 + 1] + gb.y;
                const float o0 = z0 / (1.0f + __expf(-z0));
                const float o1 = z1 / (1.0f + __expf(-z1));
                *reinterpret_cast<__half2*>(&g_gate_h[(size_t)row * DM + col]) =
                    __floats2half2_rn(o0, o1);
            }
        }
    }
}

// ---------------------------------------------------------------------------
// K1: scan (blocks 0..127) + fp16 GEMM (blocks 128..2175)
// ---------------------------------------------------------------------------
__global__ void __launch_bounds__(256, 2) k1_kernel(
    const float* __restrict__ A, const float* __restrict__ gate_b)
{
    extern __shared__ char smemc[];
    const int tid = threadIdx.x;

    if (blockIdx.x < SCAN_GRID) {
        if (tid >= 128) return;
        const int hw = tid >> 4;
        const int chunk = blockIdx.x * 8 + hw;         // 0..1023
        const int i = tid & 15;
        const int batch = chunk >> 7;
        const int cib = chunk & 127;
        const int t0 = cib * SCAN_CHUNK;
        const int ts = (cib == 0) ? 0 : (t0 - SCAN_WARM);
        const int nsteps = t0 + SCAN_CHUNK - ts;

        float a[NS];
#pragma unroll
        for (int j = 0; j < NS; ++j) a[j] = __ldg(&A[i * NS + j]);

        const float* bxp = g_Bx + (size_t)batch * SEQ * NS;
        float* stp = g_states + (size_t)batch * SEQ * NS;

        float buf[2][4];
#pragma unroll
        for (int u = 0; u < 4; ++u) buf[0][u] = bxp[(ts + u) * NS + i];

        float s = 0.f;
        const int ngroups = nsteps >> 2;
        for (int g = 0; g < ngroups; ++g) {
            const int cur = g & 1;
            if (g + 1 < ngroups) {
                const int tn = ts + (g + 1) * 4;
#pragma unroll
                for (int u = 0; u < 4; ++u)
                    buf[cur ^ 1][u] = bxp[(tn + u) * NS + i];
            }
#pragma unroll
            for (int u = 0; u < 4; ++u) {
                const int t = ts + g * 4 + u;
                float sv[NS];
#pragma unroll
                for (int j = 0; j < NS; ++j) sv[j] = __shfl_sync(0xffffffffu, s, j, 16);
                float p0 = fmaf(a[0], sv[0], fmaf(a[1], sv[1], fmaf(a[2], sv[2], a[3] * sv[3])));
                float p1 = fmaf(a[4], sv[4], fmaf(a[5], sv[5], fmaf(a[6], sv[6], a[7] * sv[7])));
                float p2 = fmaf(a[8], sv[8], fmaf(a[9], sv[9], fmaf(a[10], sv[10], a[11] * sv[11])));
                float p3 = fmaf(a[12], sv[12], fmaf(a[13], sv[13], fmaf(a[14], sv[14], a[15] * sv[15])));
                s = tanhf(buf[cur][u] + ((p0 + p1) + (p2 + p3)));
                if (t >= t0) stp[t * NS + i] = s;
            }
        }
        return;
    }

    gemm_tile_body(blockIdx.x - SCAN_GRID, gate_b, smemc);
}

// ---------------------------------------------------------------------------
// K3: combine + LayerNorm — round-14 verbatim (all-rows-upfront loads).
// ---------------------------------------------------------------------------
__global__ void __launch_bounds__(256) combine_ln_kernel(
    const float* __restrict__ x, const float* __restrict__ C_w,
    const float* __restrict__ C_b, const float* __restrict__ Dv,
    const float* __restrict__ ln_g, const float* __restrict__ ln_b,
    float* __restrict__ out)
{
    __shared__ float st_s[8][NS];
    __shared__ float r_s[8][DM];
    __shared__ float wsum[8][8], wsq[8][8];
    __shared__ float mu_s[8], rs_s[8];

    const int tid = threadIdx.x;
    const int tok0 = blockIdx.x * 8;
    const int e0 = tid * 4;

    float4 xv[8];
    uint2  gu[8];
#pragma unroll
    for (int r = 0; r < 8; ++r) {
        const size_t t = (size_t)(tok0 + r);
        xv[r] = *reinterpret_cast<const float4*>(&x[t * DM + e0]);
        gu[r] = *reinterpret_cast<const uint2*>(&g_gate_h[t * DM + e0]);
    }

    if (tid < 128)
        st_s[tid >> 4][tid & 15] =
            g_states[(size_t)(tok0 + (tid >> 4)) * NS + (tid & 15)];

    float cw[4][NS];
#pragma unroll
    for (int j = 0; j < 4; ++j)
#pragma unroll
        for (int n4 = 0; n4 < 4; ++n4) {
            const float4 v = *reinterpret_cast<const float4*>(&C_w[(e0 + j) * NS + n4 * 4]);
            cw[j][n4 * 4 + 0] = v.x;
            cw[j][n4 * 4 + 1] = v.y;
            cw[j][n4 * 4 + 2] = v.z;
            cw[j][n4 * 4 + 3] = v.w;
        }
    const float4 cb4 = *reinterpret_cast<const float4*>(&C_b[e0]);
    const float4 dv4 = *reinterpret_cast<const float4*>(&Dv[e0]);
    __syncthreads();

    const int warp = tid >> 5, lane = tid & 31;
#pragma unroll
    for (int r = 0; r < 8; ++r) {
        const float2 g01 = __half22float2(*reinterpret_cast<const __half2*>(&gu[r].x));
        const float2 g23 = __half22float2(*reinterpret_cast<const __half2*>(&gu[r].y));

        float so[4] = {cb4.x, cb4.y, cb4.z, cb4.w};
#pragma unroll
        for (int n = 0; n < NS; ++n) {
            const float st = st_s[r][n];
            so[0] = fmaf(st, cw[0][n], so[0]);
            so[1] = fmaf(st, cw[1][n], so[1]);
            so[2] = fmaf(st, cw[2][n], so[2]);
            so[3] = fmaf(st, cw[3][n], so[3]);
        }
        so[0] = fmaf(dv4.x, xv[r].x, so[0]);
        so[1] = fmaf(dv4.y, xv[r].y, so[1]);
        so[2] = fmaf(dv4.z, xv[r].z, so[2]);
        so[3] = fmaf(dv4.w, xv[r].w, so[3]);

        float4 rr;
        rr.x = fmaf(g01.x, so[0] - xv[r].x, xv[r].x) + xv[r].x;
        rr.y = fmaf(g01.y, so[1] - xv[r].y, xv[r].y) + xv[r].y;
        rr.z = fmaf(g23.x, so[2] - xv[r].z, xv[r].z) + xv[r].z;
        rr.w = fmaf(g23.y, so[3] - xv[r].w, xv[r].w) + xv[r].w;
        *reinterpret_cast<float4*>(&r_s[r][e0]) = rr;

        float ps = (rr.x + rr.y) + (rr.z + rr.w);
        float pq = fmaf(rr.x, rr.x, rr.y * rr.y) + fmaf(rr.z, rr.z, rr.w * rr.w);
#pragma unroll
        for (int off = 16; off; off >>= 1) {
            ps += __shfl_xor_sync(0xffffffffu, ps, off);
            pq += __shfl_xor_sync(0xffffffffu, pq, off);
        }
        if (lane == 0) { wsum[r][warp] = ps; wsq[r][warp] = pq; }
    }
    __syncthreads();

    if (tid < 8) {
        float s = 0.f, s2 = 0.f;
#pragma unroll
        for (int w = 0; w < 8; ++w) { s += wsum[tid][w]; s2 += wsq[tid][w]; }
        const float mu = s * (1.0f / DM);
        float var = s2 * (1.0f / DM) - mu * mu;
        var = fmaxf(var, 0.f);
        mu_s[tid] = mu;
        rs_s[tid] = rsqrtf(var + 1e-5f);
    }
    __syncthreads();

    const float4 lg4 = *reinterpret_cast<const float4*>(&ln_g[e0]);
    const float4 lb4 = *reinterpret_cast<const float4*>(&ln_b[e0]);
#pragma unroll
    for (int r = 0; r < 8; ++r) {
        const size_t t = (size_t)(tok0 + r);
        const float mu = mu_s[r], rs = rs_s[r];
        const float4 rr = *reinterpret_cast<const float4*>(&r_s[r][e0]);
        float4 o;
        o.x = (rr.x - mu) * rs * lg4.x + lb4.x;
        o.y = (rr.y - mu) * rs * lg4.y + lb4.y;
        o.z = (rr.z - mu) * rs * lg4.z + lb4.z;
        o.w = (rr.w - mu) * rs * lg4.w + lb4.w;
        *reinterpret_cast<float4*>(&out[t * DM + e0]) = o;
    }
}

// ---------------------------------------------------------------------------
extern "C" void kernel_launch(void* const* d_in, const int* in_sizes, int n_in,
                              void* d_out, int out_size)
{
    const float* x      = (const float*)d_in[0];
    const float* A      = (const float*)d_in[1];
    const float* B_w    = (const float*)d_in[2];
    const float* B_b    = (const float*)d_in[3];
    const float* C_w    = (const float*)d_in[4];
    const float* C_b    = (const float*)d_in[5];
    const float* Dv     = (const float*)d_in[6];
    const float* gate_w = (const float*)d_in[7];
    const float* gate_b = (const float*)d_in[8];
    const float* ln_g   = (const float*)d_in[9];
    const float* ln_b   = (const float*)d_in[10];
    float* out = (float*)d_out;

    cudaFuncSetAttribute(prep_kernel, cudaFuncAttributeMaxDynamicSharedMemorySize,
                         NS * DM * (int)sizeof(float));
    cudaFuncSetAttribute(k1_kernel, cudaFuncAttributeMaxDynamicSharedMemorySize,
                         GEMM_SMEM);

    prep_kernel<<<BX_GRID + GWCVT_GRID, 256, NS * DM * sizeof(float)>>>(
        x, B_w, B_b, gate_w);
    k1_kernel<<<SCAN_GRID + GEMM_BLOCKS, 256, GEMM_SMEM>>>(A, gate_b);
    combine_ln_kernel<<<T_TOK / 8, 256>>>(x, C_w, C_b, Dv, ln_g, ln_b, out);
}

// round 16
// speedup vs baseline: 1.3249x; 1.0106x over previous
#include <cuda_runtime.h>
#include <cuda_fp16.h>
#include <math.h>

// ---------------------------------------------------------------------------
// SimplifiedSSMLayer: B=8, S=4096, D_MODEL=1024, D_STATE=16
// Round 16:
//   K0 = bx blocks (0..255, pure) + x->fp16 stream blocks (256..767)
//        + gate_w->fp16 (768..771)
//   K1 = scan (128 blocks) + fp16 GEMM m16n8k16 (2048 tiles)  [round-15]
//   K3 = combine+LN, x read as fp16 from g_x_h
// ---------------------------------------------------------------------------

#define BATCH   8
#define SEQ     4096
#define DM      1024
#define NS      16
#define T_TOK   (BATCH*SEQ)          // 32768

__device__ float  g_Bx[T_TOK * NS];              // 2 MB
__device__ float  g_states[T_TOK * NS];          // 2 MB
__device__ __half g_gate_h[(size_t)T_TOK * DM];  // 64 MB
__device__ __half g_x_h[(size_t)T_TOK * DM];     // 64 MB
__device__ __half g_gw_h[DM * DM];               // 2 MB

#define BX_GRID 256
#define XCVT_GRID 512
#define GWCVT_GRID 4
#define PREP_BLOCKS (BX_GRID + XCVT_GRID + GWCVT_GRID)   // 772

#define GTM 128
#define GTN 128
#define GBK 32
#define GSTAGES (DM / GBK)                // 32
#define GEMM_BLOCKS 2048

#define ROWH 40                           // halves per row (80B, conflict-free)
#define A_HALVES (GTM * ROWH)             // 5120
#define STAGE_HALVES (2 * A_HALVES)       // 10240
#define STAGE_BYTES (STAGE_HALVES * 2)    // 20480
#define NPIPE 3
#define GEMM_SMEM (NPIPE * STAGE_BYTES)   // 61440

#define SCAN_CHUNK 32
#define SCAN_WARM  16
#define SCAN_GRID 128

__device__ __forceinline__ unsigned smem_u32(const void* p) {
    unsigned a;
    asm("{ .reg .u64 t; cvta.to.shared.u64 t, %1; cvt.u32.u64 %0, t; }"
        : "=r"(a) : "l"(p));
    return a;
}
__device__ __forceinline__ void cp16(unsigned dst, const void* src) {
    asm volatile("cp.async.cg.shared.global [%0], [%1], 16;"
                 :: "r"(dst), "l"(src) : "memory");
}
__device__ __forceinline__ void ldsm4(unsigned& r0, unsigned& r1,
                                      unsigned& r2, unsigned& r3, unsigned a) {
    asm volatile("ldmatrix.sync.aligned.m8n8.x4.shared.b16 {%0,%1,%2,%3}, [%4];"
                 : "=r"(r0), "=r"(r1), "=r"(r2), "=r"(r3) : "r"(a));
}

// ---------------------------------------------------------------------------
// K0: bx (0..255) | x->fp16 stream (256..767) | gate_w->fp16 (768..771)
// ---------------------------------------------------------------------------
__global__ void __launch_bounds__(256) prep_kernel(
    const float* __restrict__ x,
    const float* __restrict__ B_w, const float* __restrict__ B_b,
    const float* __restrict__ gate_w)
{
    extern __shared__ float smemf[];
    const int tid = threadIdx.x;

    if (blockIdx.x >= BX_GRID + XCVT_GRID) {
        // gate_w -> fp16: 4 blocks
        const int b = blockIdx.x - (BX_GRID + XCVT_GRID);
        const int base = b * 65536;
#pragma unroll 4
        for (int q = 0; q < 256; ++q) {
            const int idx = base + q * 256 + tid;
            const float4 v = *reinterpret_cast<const float4*>(&gate_w[(size_t)idx * 4]);
            uint2 h;
            *reinterpret_cast<__half2*>(&h.x) = __floats2half2_rn(v.x, v.y);
            *reinterpret_cast<__half2*>(&h.y) = __floats2half2_rn(v.z, v.w);
            *reinterpret_cast<uint2*>(&g_gw_h[(size_t)idx * 4]) = h;
        }
        return;
    }

    if (blockIdx.x >= BX_GRID) {
        // x -> fp16 grid-stride stream: 512 blocks, 8M float4 total
        const int b = blockIdx.x - BX_GRID;
        const size_t total4 = (size_t)T_TOK * DM / 4;   // 8388608
        for (size_t idx = (size_t)b * 256 + tid; idx < total4;
             idx += (size_t)XCVT_GRID * 256) {
            const float4 v = *reinterpret_cast<const float4*>(&x[idx * 4]);
            uint2 h;
            *reinterpret_cast<__half2*>(&h.x) = __floats2half2_rn(v.x, v.y);
            *reinterpret_cast<__half2*>(&h.y) = __floats2half2_rn(v.z, v.w);
            *reinterpret_cast<uint2*>(&g_x_h[idx * 4]) = h;
        }
        return;
    }

    // bx (pure, round-13 form)
    float* Bw_s = smemf;
    for (int i = tid; i < (NS * DM) / 4; i += 256)
        reinterpret_cast<float4*>(Bw_s)[i] = reinterpret_cast<const float4*>(B_w)[i];
    __syncthreads();

    const int w = tid >> 5, lane = tid & 31;
    const int tbase = blockIdx.x * 128 + w * 16;

    for (int g = 0; g < 4; ++g) {
        const int t0 = tbase + g * 4;
        float acc[4][NS];
#pragma unroll
        for (int tt = 0; tt < 4; ++tt)
#pragma unroll
            for (int n = 0; n < NS; ++n) acc[tt][n] = 0.f;

#pragma unroll 2
        for (int c = 0; c < 8; ++c) {
            const int k0 = c * 128 + lane * 4;
            float4 xv[4];
#pragma unroll
            for (int tt = 0; tt < 4; ++tt)
                xv[tt] = *reinterpret_cast<const float4*>(&x[(size_t)(t0 + tt) * DM + k0]);
#pragma unroll
            for (int n = 0; n < NS; ++n) {
                const float4 bw = *reinterpret_cast<const float4*>(&Bw_s[n * DM + k0]);
#pragma unroll
                for (int tt = 0; tt < 4; ++tt) {
                    acc[tt][n] = fmaf(xv[tt].x, bw.x, acc[tt][n]);
                    acc[tt][n] = fmaf(xv[tt].y, bw.y, acc[tt][n]);
                    acc[tt][n] = fmaf(xv[tt].z, bw.z, acc[tt][n]);
                    acc[tt][n] = fmaf(xv[tt].w, bw.w, acc[tt][n]);
                }
            }
        }
#pragma unroll
        for (int tt = 0; tt < 4; ++tt) {
            float outv = 0.f;
#pragma unroll
            for (int n = 0; n < NS; ++n) {
                float v = acc[tt][n];
                v += __shfl_xor_sync(0xffffffffu, v, 16);
                v += __shfl_xor_sync(0xffffffffu, v, 8);
                v += __shfl_xor_sync(0xffffffffu, v, 4);
                v += __shfl_xor_sync(0xffffffffu, v, 2);
                v += __shfl_xor_sync(0xffffffffu, v, 1);
                if (lane == n) outv = v;
            }
            if (lane < NS)
                g_Bx[(size_t)(t0 + tt) * NS + lane] = outv + B_b[lane];
        }
    }
}

// ---------------------------------------------------------------------------
// fp16 GEMM tile body (round-15 verbatim)
// ---------------------------------------------------------------------------
__device__ __forceinline__ void gemm_tile_body(
    int tile, const float* __restrict__ gate_b, char* smem)
{
    const int m0 = (tile >> 3) * GTM;
    const int n0 = (tile & 7) * GTN;

    const int tid = threadIdx.x;
    const int wid = tid >> 5;
    const int lane = tid & 31;
    const int wm = (wid & 3) * 32;
    const int wn = (wid >> 2) * 64;
    const int lq = lane >> 2;
    const int lr = lane & 3;

    const unsigned sbase = smem_u32(smem);

    const int a_row = wm + (lane & 7) + ((lane >> 3) & 1) * 8;   // + mi*16
    const int a_kxh = (lane >> 4) * 8;
    const int b_row = wn + (lane & 7) + ((lane >> 4) & 1) * 8;   // + nip*16
    const int b_kxh = ((lane >> 3) & 1) * 8;

    auto cp_stage = [&](int s) {
        const int kc = s * GBK;
        const unsigned sA = sbase + (unsigned)(s % NPIPE) * STAGE_BYTES;
        const unsigned sB = sA + A_HALVES * 2;
#pragma unroll
        for (int q = 0; q < 2; ++q) {
            const int j = tid + 256 * q;   // 0..511
            const int row = j >> 2;
            const int kg = j & 3;
            cp16(sA + row * (ROWH * 2) + kg * 16,
                 &g_x_h[(size_t)(m0 + row) * DM + kc + kg * 8]);
            cp16(sB + row * (ROWH * 2) + kg * 16,
                 &g_gw_h[(size_t)(n0 + row) * DM + kc + kg * 8]);
        }
        asm volatile("cp.async.commit_group;" ::: "memory");
    };

    float c[2][8][4];
#pragma unroll
    for (int mi = 0; mi < 2; ++mi)
#pragma unroll
        for (int ni = 0; ni < 8; ++ni)
#pragma unroll
            for (int r = 0; r < 4; ++r) c[mi][ni][r] = 0.f;

    cp_stage(0);
    cp_stage(1);

    for (int s = 0; s < GSTAGES; ++s) {
        asm volatile("cp.async.wait_group 1;" ::: "memory");
        __syncthreads();

        const unsigned stg = sbase + (unsigned)(s % NPIPE) * STAGE_BYTES;
        const unsigned aAddr0 = stg + (unsigned)(a_row * ROWH + a_kxh) * 2u;
        const unsigned bAddr0 = stg + (unsigned)(A_HALVES + b_row * ROWH + b_kxh) * 2u;

#pragma unroll
        for (int ks = 0; ks < 2; ++ks) {
            const int k0h = ks * 16;
            unsigned af[2][4];
#pragma unroll
            for (int mi = 0; mi < 2; ++mi)
                ldsm4(af[mi][0], af[mi][1], af[mi][2], af[mi][3],
                      aAddr0 + (unsigned)(mi * 16 * ROWH + k0h) * 2u);
            unsigned bf[8][2];
#pragma unroll
            for (int nip = 0; nip < 4; ++nip)
                ldsm4(bf[nip * 2][0], bf[nip * 2][1],
                      bf[nip * 2 + 1][0], bf[nip * 2 + 1][1],
                      bAddr0 + (unsigned)(nip * 16 * ROWH + k0h) * 2u);
#pragma unroll
            for (int mi = 0; mi < 2; ++mi)
#pragma unroll
                for (int ni = 0; ni < 8; ++ni) {
                    asm volatile(
                        "mma.sync.aligned.m16n8k16.row.col.f32.f16.f16.f32 "
                        "{%0,%1,%2,%3}, {%4,%5,%6,%7}, {%8,%9}, {%0,%1,%2,%3};"
                        : "+f"(c[mi][ni][0]), "+f"(c[mi][ni][1]),
                          "+f"(c[mi][ni][2]), "+f"(c[mi][ni][3])
                        : "r"(af[mi][0]), "r"(af[mi][1]),
                          "r"(af[mi][2]), "r"(af[mi][3]),
                          "r"(bf[ni][0]), "r"(bf[ni][1]));
                }
        }
        if (s + 2 < GSTAGES) cp_stage(s + 2);
    }

#pragma unroll
    for (int ni = 0; ni < 8; ++ni) {
        const int col = n0 + wn + ni * 8 + lr * 2;
        const float2 gb = *reinterpret_cast<const float2*>(&gate_b[col]);
#pragma unroll
        for (int mi = 0; mi < 2; ++mi) {
            const int row0 = m0 + wm + mi * 16 + lq;
#pragma unroll
            for (int h = 0; h < 2; ++h) {
                const int row = row0 + h * 8;
                float z0 = c[mi][ni][h * 2 + 0] + gb.x;
                float z1 = c[mi][ni][h * 2 + 1] + gb.y;
                const float o0 = z0 / (1.0f + __expf(-z0));
                const float o1 = z1 / (1.0f + __expf(-z1));
                *reinterpret_cast<__half2*>(&g_gate_h[(size_t)row * DM + col]) =
                    __floats2half2_rn(o0, o1);
            }
        }
    }
}

// ---------------------------------------------------------------------------
// K1: scan (blocks 0..127) + fp16 GEMM (blocks 128..2175)
// ---------------------------------------------------------------------------
__global__ void __launch_bounds__(256, 2) k1_kernel(
    const float* __restrict__ A, const float* __restrict__ gate_b)
{
    extern __shared__ char smemc[];
    const int tid = threadIdx.x;

    if (blockIdx.x < SCAN_GRID) {
        if (tid >= 128) return;
        const int hw = tid >> 4;
        const int chunk = blockIdx.x * 8 + hw;
        const int i = tid & 15;
        const int batch = chunk >> 7;
        const int cib = chunk & 127;
        const int t0 = cib * SCAN_CHUNK;
        const int ts = (cib == 0) ? 0 : (t0 - SCAN_WARM);
        const int nsteps = t0 + SCAN_CHUNK - ts;

        float a[NS];
#pragma unroll
        for (int j = 0; j < NS; ++j) a[j] = __ldg(&A[i * NS + j]);

        const float* bxp = g_Bx + (size_t)batch * SEQ * NS;
        float* stp = g_states + (size_t)batch * SEQ * NS;

        float buf[2][4];
#pragma unroll
        for (int u = 0; u < 4; ++u) buf[0][u] = bxp[(ts + u) * NS + i];

        float s = 0.f;
        const int ngroups = nsteps >> 2;
        for (int g = 0; g < ngroups; ++g) {
            const int cur = g & 1;
            if (g + 1 < ngroups) {
                const int tn = ts + (g + 1) * 4;
#pragma unroll
                for (int u = 0; u < 4; ++u)
                    buf[cur ^ 1][u] = bxp[(tn + u) * NS + i];
            }
#pragma unroll
            for (int u = 0; u < 4; ++u) {
                const int t = ts + g * 4 + u;
                float sv[NS];
#pragma unroll
                for (int j = 0; j < NS; ++j) sv[j] = __shfl_sync(0xffffffffu, s, j, 16);
                float p0 = fmaf(a[0], sv[0], fmaf(a[1], sv[1], fmaf(a[2], sv[2], a[3] * sv[3])));
                float p1 = fmaf(a[4], sv[4], fmaf(a[5], sv[5], fmaf(a[6], sv[6], a[7] * sv[7])));
                float p2 = fmaf(a[8], sv[8], fmaf(a[9], sv[9], fmaf(a[10], sv[10], a[11] * sv[11])));
                float p3 = fmaf(a[12], sv[12], fmaf(a[13], sv[13], fmaf(a[14], sv[14], a[15] * sv[15])));
                s = tanhf(buf[cur][u] + ((p0 + p1) + (p2 + p3)));
                if (t >= t0) stp[t * NS + i] = s;
            }
        }
        return;
    }

    gemm_tile_body(blockIdx.x - SCAN_GRID, gate_b, smemc);
}

// ---------------------------------------------------------------------------
// K3: combine + LayerNorm — x read as fp16 (g_x_h), upfront loads.
// ---------------------------------------------------------------------------
__global__ void __launch_bounds__(256) combine_ln_kernel(
    const float* __restrict__ C_w, const float* __restrict__ C_b,
    const float* __restrict__ Dv,
    const float* __restrict__ ln_g, const float* __restrict__ ln_b,
    float* __restrict__ out)
{
    __shared__ float st_s[8][NS];
    __shared__ float r_s[8][DM];
    __shared__ float wsum[8][8], wsq[8][8];
    __shared__ float mu_s[8], rs_s[8];

    const int tid = threadIdx.x;
    const int tok0 = blockIdx.x * 8;
    const int e0 = tid * 4;

    uint2 xu[8], gu[8];
#pragma unroll
    for (int r = 0; r < 8; ++r) {
        const size_t t = (size_t)(tok0 + r);
        xu[r] = *reinterpret_cast<const uint2*>(&g_x_h[t * DM + e0]);
        gu[r] = *reinterpret_cast<const uint2*>(&g_gate_h[t * DM + e0]);
    }

    if (tid < 128)
        st_s[tid >> 4][tid & 15] =
            g_states[(size_t)(tok0 + (tid >> 4)) * NS + (tid & 15)];

    float cw[4][NS];
#pragma unroll
    for (int j = 0; j < 4; ++j)
#pragma unroll
        for (int n4 = 0; n4 < 4; ++n4) {
            const float4 v = *reinterpret_cast<const float4*>(&C_w[(e0 + j) * NS + n4 * 4]);
            cw[j][n4 * 4 + 0] = v.x;
            cw[j][n4 * 4 + 1] = v.y;
            cw[j][n4 * 4 + 2] = v.z;
            cw[j][n4 * 4 + 3] = v.w;
        }
    const float4 cb4 = *reinterpret_cast<const float4*>(&C_b[e0]);
    const float4 dv4 = *reinterpret_cast<const float4*>(&Dv[e0]);
    __syncthreads();

    const int warp = tid >> 5, lane = tid & 31;
#pragma unroll
    for (int r = 0; r < 8; ++r) {
        const float2 x01 = __half22float2(*reinterpret_cast<const __half2*>(&xu[r].x));
        const float2 x23 = __half22float2(*reinterpret_cast<const __half2*>(&xu[r].y));
        const float2 g01 = __half22float2(*reinterpret_cast<const __half2*>(&gu[r].x));
        const float2 g23 = __half22float2(*reinterpret_cast<const __half2*>(&gu[r].y));
        const float xv0 = x01.x, xv1 = x01.y, xv2 = x23.x, xv3 = x23.y;

        float so[4] = {cb4.x, cb4.y, cb4.z, cb4.w};
#pragma unroll
        for (int n = 0; n < NS; ++n) {
            const float st = st_s[r][n];
            so[0] = fmaf(st, cw[0][n], so[0]);
            so[1] = fmaf(st, cw[1][n], so[1]);
            so[2] = fmaf(st, cw[2][n], so[2]);
            so[3] = fmaf(st, cw[3][n], so[3]);
        }
        so[0] = fmaf(dv4.x, xv0, so[0]);
        so[1] = fmaf(dv4.y, xv1, so[1]);
        so[2] = fmaf(dv4.z, xv2, so[2]);
        so[3] = fmaf(dv4.w, xv3, so[3]);

        float4 rr;
        rr.x = fmaf(g01.x, so[0] - xv0, xv0) + xv0;
        rr.y = fmaf(g01.y, so[1] - xv1, xv1) + xv1;
        rr.z = fmaf(g23.x, so[2] - xv2, xv2) + xv2;
        rr.w = fmaf(g23.y, so[3] - xv3, xv3) + xv3;
        *reinterpret_cast<float4*>(&r_s[r][e0]) = rr;

        float ps = (rr.x + rr.y) + (rr.z + rr.w);
        float pq = fmaf(rr.x, rr.x, rr.y * rr.y) + fmaf(rr.z, rr.z, rr.w * rr.w);
#pragma unroll
        for (int off = 16; off; off >>= 1) {
            ps += __shfl_xor_sync(0xffffffffu, ps, off);
            pq += __shfl_xor_sync(0xffffffffu, pq, off);
        }
        if (lane == 0) { wsum[r][warp] = ps; wsq[r][warp] = pq; }
    }
    __syncthreads();

    if (tid < 8) {
        float s = 0.f, s2 = 0.f;
#pragma unroll
        for (int w = 0; w < 8; ++w) { s += wsum[tid][w]; s2 += wsq[tid][w]; }
        const float mu = s * (1.0f / DM);
        float var = s2 * (1.0f / DM) - mu * mu;
        var = fmaxf(var, 0.f);
        mu_s[tid] = mu;
        rs_s[tid] = rsqrtf(var + 1e-5f);
    }
    __syncthreads();

    const float4 lg4 = *reinterpret_cast<const float4*>(&ln_g[e0]);
    const float4 lb4 = *reinterpret_cast<const float4*>(&ln_b[e0]);
#pragma unroll
    for (int r = 0; r < 8; ++r) {
        const size_t t = (size_t)(tok0 + r);
        const float mu = mu_s[r], rs = rs_s[r];
        const float4 rr = *reinterpret_cast<const float4*>(&r_s[r][e0]);
        float4 o;
        o.x = (rr.x - mu) * rs * lg4.x + lb4.x;
        o.y = (rr.y - mu) * rs * lg4.y + lb4.y;
        o.z = (rr.z - mu) * rs * lg4.z + lb4.z;
        o.w = (rr.w - mu) * rs * lg4.w + lb4.w;
        *reinterpret_cast<float4*>(&out[t * DM + e0]) = o;
    }
}

// ---------------------------------------------------------------------------
extern "C" void kernel_launch(void* const* d_in, const int* in_sizes, int n_in,
                              void* d_out, int out_size)
{
    const float* x      = (const float*)d_in[0];
    const float* A      = (const float*)d_in[1];
    const float* B_w    = (const float*)d_in[2];
    const float* B_b    = (const float*)d_in[3];
    const float* C_w    = (const float*)d_in[4];
    const float* C_b    = (const float*)d_in[5];
    const float* Dv     = (const float*)d_in[6];
    const float* gate_w = (const float*)d_in[7];
    const float* gate_b = (const float*)d_in[8];
    const float* ln_g   = (const float*)d_in[9];
    const float* ln_b   = (const float*)d_in[10];
    float* out = (float*)d_out;

    cudaFuncSetAttribute(prep_kernel, cudaFuncAttributeMaxDynamicSharedMemorySize,
                         NS * DM * (int)sizeof(float));
    cudaFuncSetAttribute(k1_kernel, cudaFuncAttributeMaxDynamicSharedMemorySize,
                         GEMM_SMEM);

    prep_kernel<<<PREP_BLOCKS, 256, NS * DM * sizeof(float)>>>(x, B_w, B_b, gate_w);
    k1_kernel<<<SCAN_GRID + GEMM_BLOCKS, 256, GEMM_SMEM>>>(A, gate_b);
    combine_ln_kernel<<<T_TOK / 8, 256>>>(C_w, C_b, Dv, ln_g, ln_b, out);
}

// round 17
// speedup vs baseline: 1.4093x; 1.0637x over previous
#include <cuda_runtime.h>
#include <cuda_fp16.h>
#include <math.h>

// ---------------------------------------------------------------------------
// SimplifiedSSMLayer: B=8, S=4096, D_MODEL=1024, D_STATE=16
// Round 17:
//   K0 = bx blocks (emit x->fp16 from registers) + gate_w->fp16 (round-15)
//   K1 = scan (128) + fp16 GEMM m16n8k16, BK=64 (16 stages, half the barriers)
//   K3 = combine+LN, fp16 x/gate reads (round-16)
// ---------------------------------------------------------------------------

#define BATCH   8
#define SEQ     4096
#define DM      1024
#define NS      16
#define T_TOK   (BATCH*SEQ)          // 32768

__device__ float  g_Bx[T_TOK * NS];              // 2 MB
__device__ float  g_states[T_TOK * NS];          // 2 MB
__device__ __half g_gate_h[(size_t)T_TOK * DM];  // 64 MB
__device__ __half g_x_h[(size_t)T_TOK * DM];     // 64 MB
__device__ __half g_gw_h[DM * DM];               // 2 MB

#define BX_GRID 256
#define GWCVT_GRID 4

#define GTM 128
#define GTN 128
#define GBK 64
#define GSTAGES (DM / GBK)                // 16
#define GEMM_BLOCKS 2048

#define ROWH 72                           // 64 k-halves + 8 pad (144B rows)
#define A_HALVES (GTM * ROWH)             // 9216
#define STAGE_HALVES (2 * A_HALVES)       // 18432
#define STAGE_BYTES (STAGE_HALVES * 2)    // 36864
#define NPIPE 3
#define GEMM_SMEM (NPIPE * STAGE_BYTES)   // 110592 -> 2 CTAs/SM

#define SCAN_CHUNK 32
#define SCAN_WARM  16
#define SCAN_GRID 128

__device__ __forceinline__ unsigned smem_u32(const void* p) {
    unsigned a;
    asm("{ .reg .u64 t; cvta.to.shared.u64 t, %1; cvt.u32.u64 %0, t; }"
        : "=r"(a) : "l"(p));
    return a;
}
__device__ __forceinline__ void cp16(unsigned dst, const void* src) {
    asm volatile("cp.async.cg.shared.global [%0], [%1], 16;"
                 :: "r"(dst), "l"(src) : "memory");
}
__device__ __forceinline__ void ldsm4(unsigned& r0, unsigned& r1,
                                      unsigned& r2, unsigned& r3, unsigned a) {
    asm volatile("ldmatrix.sync.aligned.m8n8.x4.shared.b16 {%0,%1,%2,%3}, [%4];"
                 : "=r"(r0), "=r"(r1), "=r"(r2), "=r"(r3) : "r"(a));
}

// ---------------------------------------------------------------------------
// K0: bx + x->fp16 (blocks 0..255) and gate_w->fp16 (blocks 256..259)
// ---------------------------------------------------------------------------
__global__ void __launch_bounds__(256) prep_kernel(
    const float* __restrict__ x,
    const float* __restrict__ B_w, const float* __restrict__ B_b,
    const float* __restrict__ gate_w)
{
    extern __shared__ float smemf[];
    const int tid = threadIdx.x;

    if (blockIdx.x >= BX_GRID) {
        const int b = blockIdx.x - BX_GRID;
        const int base = b * 65536;
#pragma unroll 4
        for (int q = 0; q < 256; ++q) {
            const int idx = base + q * 256 + tid;
            const float4 v = *reinterpret_cast<const float4*>(&gate_w[(size_t)idx * 4]);
            uint2 h;
            *reinterpret_cast<__half2*>(&h.x) = __floats2half2_rn(v.x, v.y);
            *reinterpret_cast<__half2*>(&h.y) = __floats2half2_rn(v.z, v.w);
            *reinterpret_cast<uint2*>(&g_gw_h[(size_t)idx * 4]) = h;
        }
        return;
    }

    float* Bw_s = smemf;
    for (int i = tid; i < (NS * DM) / 4; i += 256)
        reinterpret_cast<float4*>(Bw_s)[i] = reinterpret_cast<const float4*>(B_w)[i];
    __syncthreads();

    const int w = tid >> 5, lane = tid & 31;
    const int tbase = blockIdx.x * 128 + w * 16;

    for (int g = 0; g < 4; ++g) {
        const int t0 = tbase + g * 4;
        float acc[4][NS];
#pragma unroll
        for (int tt = 0; tt < 4; ++tt)
#pragma unroll
            for (int n = 0; n < NS; ++n) acc[tt][n] = 0.f;

#pragma unroll 2
        for (int c = 0; c < 8; ++c) {
            const int k0 = c * 128 + lane * 4;
            float4 xv[4];
#pragma unroll
            for (int tt = 0; tt < 4; ++tt) {
                xv[tt] = *reinterpret_cast<const float4*>(&x[(size_t)(t0 + tt) * DM + k0]);
                uint2 h;
                *reinterpret_cast<__half2*>(&h.x) = __floats2half2_rn(xv[tt].x, xv[tt].y);
                *reinterpret_cast<__half2*>(&h.y) = __floats2half2_rn(xv[tt].z, xv[tt].w);
                *reinterpret_cast<uint2*>(&g_x_h[(size_t)(t0 + tt) * DM + k0]) = h;
            }
#pragma unroll
            for (int n = 0; n < NS; ++n) {
                const float4 bw = *reinterpret_cast<const float4*>(&Bw_s[n * DM + k0]);
#pragma unroll
                for (int tt = 0; tt < 4; ++tt) {
                    acc[tt][n] = fmaf(xv[tt].x, bw.x, acc[tt][n]);
                    acc[tt][n] = fmaf(xv[tt].y, bw.y, acc[tt][n]);
                    acc[tt][n] = fmaf(xv[tt].z, bw.z, acc[tt][n]);
                    acc[tt][n] = fmaf(xv[tt].w, bw.w, acc[tt][n]);
                }
            }
        }
#pragma unroll
        for (int tt = 0; tt < 4; ++tt) {
            float outv = 0.f;
#pragma unroll
            for (int n = 0; n < NS; ++n) {
                float v = acc[tt][n];
                v += __shfl_xor_sync(0xffffffffu, v, 16);
                v += __shfl_xor_sync(0xffffffffu, v, 8);
                v += __shfl_xor_sync(0xffffffffu, v, 4);
                v += __shfl_xor_sync(0xffffffffu, v, 2);
                v += __shfl_xor_sync(0xffffffffu, v, 1);
                if (lane == n) outv = v;
            }
            if (lane < NS)
                g_Bx[(size_t)(t0 + tt) * NS + lane] = outv + B_b[lane];
        }
    }
}

// ---------------------------------------------------------------------------
// fp16 GEMM tile body: 128x128 tile, BK=64, 3-stage cp.async, m16n8k16.
// ---------------------------------------------------------------------------
__device__ __forceinline__ void gemm_tile_body(
    int tile, const float* __restrict__ gate_b, char* smem)
{
    const int m0 = (tile >> 3) * GTM;
    const int n0 = (tile & 7) * GTN;

    const int tid = threadIdx.x;
    const int wid = tid >> 5;
    const int lane = tid & 31;
    const int wm = (wid & 3) * 32;
    const int wn = (wid >> 2) * 64;
    const int lq = lane >> 2;
    const int lr = lane & 3;

    const unsigned sbase = smem_u32(smem);

    const int a_row = wm + (lane & 7) + ((lane >> 3) & 1) * 8;   // + mi*16
    const int a_kxh = (lane >> 4) * 8;
    const int b_row = wn + (lane & 7) + ((lane >> 4) & 1) * 8;   // + nip*16
    const int b_kxh = ((lane >> 3) & 1) * 8;

    auto cp_stage = [&](int s) {
        const int kc = s * GBK;
        const unsigned sA = sbase + (unsigned)(s % NPIPE) * STAGE_BYTES;
        const unsigned sB = sA + A_HALVES * 2;
#pragma unroll
        for (int q = 0; q < 4; ++q) {
            const int j = tid + 256 * q;   // 0..1023
            const int row = j >> 3;        // 8 chunks of 8 halves per row
            const int kg = j & 7;
            cp16(sA + row * (ROWH * 2) + kg * 16,
                 &g_x_h[(size_t)(m0 + row) * DM + kc + kg * 8]);
            cp16(sB + row * (ROWH * 2) + kg * 16,
                 &g_gw_h[(size_t)(n0 + row) * DM + kc + kg * 8]);
        }
        asm volatile("cp.async.commit_group;" ::: "memory");
    };

    float c[2][8][4];
#pragma unroll
    for (int mi = 0; mi < 2; ++mi)
#pragma unroll
        for (int ni = 0; ni < 8; ++ni)
#pragma unroll
            for (int r = 0; r < 4; ++r) c[mi][ni][r] = 0.f;

    cp_stage(0);
    cp_stage(1);

    for (int s = 0; s < GSTAGES; ++s) {
        asm volatile("cp.async.wait_group 1;" ::: "memory");
        __syncthreads();

        const unsigned stg = sbase + (unsigned)(s % NPIPE) * STAGE_BYTES;
        const unsigned aAddr0 = stg + (unsigned)(a_row * ROWH + a_kxh) * 2u;
        const unsigned bAddr0 = stg + (unsigned)(A_HALVES + b_row * ROWH + b_kxh) * 2u;

#pragma unroll
        for (int ks = 0; ks < 4; ++ks) {
            const int k0h = ks * 16;
            unsigned af[2][4];
#pragma unroll
            for (int mi = 0; mi < 2; ++mi)
                ldsm4(af[mi][0], af[mi][1], af[mi][2], af[mi][3],
                      aAddr0 + (unsigned)(mi * 16 * ROWH + k0h) * 2u);
            unsigned bf[8][2];
#pragma unroll
            for (int nip = 0; nip < 4; ++nip)
                ldsm4(bf[nip * 2][0], bf[nip * 2][1],
                      bf[nip * 2 + 1][0], bf[nip * 2 + 1][1],
                      bAddr0 + (unsigned)(nip * 16 * ROWH + k0h) * 2u);
#pragma unroll
            for (int mi = 0; mi < 2; ++mi)
#pragma unroll
                for (int ni = 0; ni < 8; ++ni) {
                    asm volatile(
                        "mma.sync.aligned.m16n8k16.row.col.f32.f16.f16.f32 "
                        "{%0,%1,%2,%3}, {%4,%5,%6,%7}, {%8,%9}, {%0,%1,%2,%3};"
                        : "+f"(c[mi][ni][0]), "+f"(c[mi][ni][1]),
                          "+f"(c[mi][ni][2]), "+f"(c[mi][ni][3])
                        : "r"(af[mi][0]), "r"(af[mi][1]),
                          "r"(af[mi][2]), "r"(af[mi][3]),
                          "r"(bf[ni][0]), "r"(bf[ni][1]));
                }
        }
        if (s + 2 < GSTAGES) cp_stage(s + 2);
    }

#pragma unroll
    for (int ni = 0; ni < 8; ++ni) {
        const int col = n0 + wn + ni * 8 + lr * 2;
        const float2 gb = *reinterpret_cast<const float2*>(&gate_b[col]);
#pragma unroll
        for (int mi = 0; mi < 2; ++mi) {
            const int row0 = m0 + wm + mi * 16 + lq;
#pragma unroll
            for (int h = 0; h < 2; ++h) {
                const int row = row0 + h * 8;
                float z0 = c[mi][ni][h * 2 + 0] + gb.x;
                float z1 = c[mi][ni][h * 2 + 1] + gb.y;
                const float o0 = z0 / (1.0f + __expf(-z0));
                const float o1 = z1 / (1.0f + __expf(-z1));
                *reinterpret_cast<__half2*>(&g_gate_h[(size_t)row * DM + col]) =
                    __floats2half2_rn(o0, o1);
            }
        }
    }
}

// ---------------------------------------------------------------------------
// K1: scan (blocks 0..127) + fp16 GEMM (blocks 128..2175)
// ---------------------------------------------------------------------------
__global__ void __launch_bounds__(256, 2) k1_kernel(
    const float* __restrict__ A, const float* __restrict__ gate_b)
{
    extern __shared__ char smemc[];
    const int tid = threadIdx.x;

    if (blockIdx.x < SCAN_GRID) {
        if (tid >= 128) return;
        const int hw = tid >> 4;
        const int chunk = blockIdx.x * 8 + hw;
        const int i = tid & 15;
        const int batch = chunk >> 7;
        const int cib = chunk & 127;
        const int t0 = cib * SCAN_CHUNK;
        const int ts = (cib == 0) ? 0 : (t0 - SCAN_WARM);
        const int nsteps = t0 + SCAN_CHUNK - ts;

        float a[NS];
#pragma unroll
        for (int j = 0; j < NS; ++j) a[j] = __ldg(&A[i * NS + j]);

        const float* bxp = g_Bx + (size_t)batch * SEQ * NS;
        float* stp = g_states + (size_t)batch * SEQ * NS;

        float buf[2][4];
#pragma unroll
        for (int u = 0; u < 4; ++u) buf[0][u] = bxp[(ts + u) * NS + i];

        float s = 0.f;
        const int ngroups = nsteps >> 2;
        for (int g = 0; g < ngroups; ++g) {
            const int cur = g & 1;
            if (g + 1 < ngroups) {
                const int tn = ts + (g + 1) * 4;
#pragma unroll
                for (int u = 0; u < 4; ++u)
                    buf[cur ^ 1][u] = bxp[(tn + u) * NS + i];
            }
#pragma unroll
            for (int u = 0; u < 4; ++u) {
                const int t = ts + g * 4 + u;
                float sv[NS];
#pragma unroll
                for (int j = 0; j < NS; ++j) sv[j] = __shfl_sync(0xffffffffu, s, j, 16);
                float p0 = fmaf(a[0], sv[0], fmaf(a[1], sv[1], fmaf(a[2], sv[2], a[3] * sv[3])));
                float p1 = fmaf(a[4], sv[4], fmaf(a[5], sv[5], fmaf(a[6], sv[6], a[7] * sv[7])));
                float p2 = fmaf(a[8], sv[8], fmaf(a[9], sv[9], fmaf(a[10], sv[10], a[11] * sv[11])));
                float p3 = fmaf(a[12], sv[12], fmaf(a[13], sv[13], fmaf(a[14], sv[14], a[15] * sv[15])));
                s = tanhf(buf[cur][u] + ((p0 + p1) + (p2 + p3)));
                if (t >= t0) stp[t * NS + i] = s;
            }
        }
        return;
    }

    gemm_tile_body(blockIdx.x - SCAN_GRID, gate_b, smemc);
}

// ---------------------------------------------------------------------------
// K3: combine + LayerNorm — fp16 x/gate reads, upfront loads (round-16).
// ---------------------------------------------------------------------------
__global__ void __launch_bounds__(256) combine_ln_kernel(
    const float* __restrict__ C_w, const float* __restrict__ C_b,
    const float* __restrict__ Dv,
    const float* __restrict__ ln_g, const float* __restrict__ ln_b,
    float* __restrict__ out)
{
    __shared__ float st_s[8][NS];
    __shared__ float r_s[8][DM];
    __shared__ float wsum[8][8], wsq[8][8];
    __shared__ float mu_s[8], rs_s[8];

    const int tid = threadIdx.x;
    const int tok0 = blockIdx.x * 8;
    const int e0 = tid * 4;

    uint2 xu[8], gu[8];
#pragma unroll
    for (int r = 0; r < 8; ++r) {
        const size_t t = (size_t)(tok0 + r);
        xu[r] = *reinterpret_cast<const uint2*>(&g_x_h[t * DM + e0]);
        gu[r] = *reinterpret_cast<const uint2*>(&g_gate_h[t * DM + e0]);
    }

    if (tid < 128)
        st_s[tid >> 4][tid & 15] =
            g_states[(size_t)(tok0 + (tid >> 4)) * NS + (tid & 15)];

    float cw[4][NS];
#pragma unroll
    for (int j = 0; j < 4; ++j)
#pragma unroll
        for (int n4 = 0; n4 < 4; ++n4) {
            const float4 v = *reinterpret_cast<const float4*>(&C_w[(e0 + j) * NS + n4 * 4]);
            cw[j][n4 * 4 + 0] = v.x;
            cw[j][n4 * 4 + 1] = v.y;
            cw[j][n4 * 4 + 2] = v.z;
            cw[j][n4 * 4 + 3] = v.w;
        }
    const float4 cb4 = *reinterpret_cast<const float4*>(&C_b[e0]);
    const float4 dv4 = *reinterpret_cast<const float4*>(&Dv[e0]);
    __syncthreads();

    const int warp = tid >> 5, lane = tid & 31;
#pragma unroll
    for (int r = 0; r < 8; ++r) {
        const float2 x01 = __half22float2(*reinterpret_cast<const __half2*>(&xu[r].x));
        const float2 x23 = __half22float2(*reinterpret_cast<const __half2*>(&xu[r].y));
        const float2 g01 = __half22float2(*reinterpret_cast<const __half2*>(&gu[r].x));
        const float2 g23 = __half22float2(*reinterpret_cast<const __half2*>(&gu[r].y));
        const float xv0 = x01.x, xv1 = x01.y, xv2 = x23.x, xv3 = x23.y;

        float so[4] = {cb4.x, cb4.y, cb4.z, cb4.w};
#pragma unroll
        for (int n = 0; n < NS; ++n) {
            const float st = st_s[r][n];
            so[0] = fmaf(st, cw[0][n], so[0]);
            so[1] = fmaf(st, cw[1][n], so[1]);
            so[2] = fmaf(st, cw[2][n], so[2]);
            so[3] = fmaf(st, cw[3][n], so[3]);
        }
        so[0] = fmaf(dv4.x, xv0, so[0]);
        so[1] = fmaf(dv4.y, xv1, so[1]);
        so[2] = fmaf(dv4.z, xv2, so[2]);
        so[3] = fmaf(dv4.w, xv3, so[3]);

        float4 rr;
        rr.x = fmaf(g01.x, so[0] - xv0, xv0) + xv0;
        rr.y = fmaf(g01.y, so[1] - xv1, xv1) + xv1;
        rr.z = fmaf(g23.x, so[2] - xv2, xv2) + xv2;
        rr.w = fmaf(g23.y, so[3] - xv3, xv3) + xv3;
        *reinterpret_cast<float4*>(&r_s[r][e0]) = rr;

        float ps = (rr.x + rr.y) + (rr.z + rr.w);
        float pq = fmaf(rr.x, rr.x, rr.y * rr.y) + fmaf(rr.z, rr.z, rr.w * rr.w);
#pragma unroll
        for (int off = 16; off; off >>= 1) {
            ps += __shfl_xor_sync(0xffffffffu, ps, off);
            pq += __shfl_xor_sync(0xffffffffu, pq, off);
        }
        if (lane == 0) { wsum[r][warp] = ps; wsq[r][warp] = pq; }
    }
    __syncthreads();

    if (tid < 8) {
        float s = 0.f, s2 = 0.f;
#pragma unroll
        for (int w = 0; w < 8; ++w) { s += wsum[tid][w]; s2 += wsq[tid][w]; }
        const float mu = s * (1.0f / DM);
        float var = s2 * (1.0f / DM) - mu * mu;
        var = fmaxf(var, 0.f);
        mu_s[tid] = mu;
        rs_s[tid] = rsqrtf(var + 1e-5f);
    }
    __syncthreads();

    const float4 lg4 = *reinterpret_cast<const float4*>(&ln_g[e0]);
    const float4 lb4 = *reinterpret_cast<const float4*>(&ln_b[e0]);
#pragma unroll
    for (int r = 0; r < 8; ++r) {
        const size_t t = (size_t)(tok0 + r);
        const float mu = mu_s[r], rs = rs_s[r];
        const float4 rr = *reinterpret_cast<const float4*>(&r_s[r][e0]);
        float4 o;
        o.x = (rr.x - mu) * rs * lg4.x + lb4.x;
        o.y = (rr.y - mu) * rs * lg4.y + lb4.y;
        o.z = (rr.z - mu) * rs * lg4.z + lb4.z;
        o.w = (rr.w - mu) * rs * lg4.w + lb4.w;
        *reinterpret_cast<float4*>(&out[t * DM + e0]) = o;
    }
}

// ---------------------------------------------------------------------------
extern "C" void kernel_launch(void* const* d_in, const int* in_sizes, int n_in,
                              void* d_out, int out_size)
{
    const float* x      = (const float*)d_in[0];
    const float* A      = (const float*)d_in[1];
    const float* B_w    = (const float*)d_in[2];
    const float* B_b    = (const float*)d_in[3];
    const float* C_w    = (const float*)d_in[4];
    const float* C_b    = (const float*)d_in[5];
    const float* Dv     = (const float*)d_in[6];
    const float* gate_w = (const float*)d_in[7];
    const float* gate_b = (const float*)d_in[8];
    const float* ln_g   = (const float*)d_in[9];
    const float* ln_b   = (const float*)d_in[10];
    float* out = (float*)d_out;

    cudaFuncSetAttribute(prep_kernel, cudaFuncAttributeMaxDynamicSharedMemorySize,
                         NS * DM * (int)sizeof(float));
    cudaFuncSetAttribute(k1_kernel, cudaFuncAttributeMaxDynamicSharedMemorySize,
                         GEMM_SMEM);

    prep_kernel<<<BX_GRID + GWCVT_GRID, 256, NS * DM * sizeof(float)>>>(
        x, B_w, B_b, gate_w);
    k1_kernel<<<SCAN_GRID + GEMM_BLOCKS, 256, GEMM_SMEM>>>(A, gate_b);
    combine_ln_kernel<<<T_TOK / 8, 256>>>(C_w, C_b, Dv, ln_g, ln_b, out);
}